// round 4
// baseline (speedup 1.0000x reference)
#include <cuda_runtime.h>
#include <cuda_bf16.h>

#define S_LEN 2048
#define EMB   1024
#define NHEAD 16
#define HDIM  64
#define BATCH 2
#define MROWS 4096   // BATCH * S_LEN

// Scratch (allocation-free rule: __device__ globals)
__device__ __align__(16) float g_q[BATCH * NHEAD * S_LEN * HDIM];   // [B,H,S,D]
__device__ __align__(16) float g_k[BATCH * NHEAD * S_LEN * HDIM];
__device__ __align__(16) float g_v[BATCH * NHEAD * S_LEN * HDIM];
__device__ __align__(16) float g_att[BATCH * S_LEN * EMB];          // [B,S,E]

// ---------------------------------------------------------------------------
// GEMM: C[M,N] = A[M,K] * W[N,K]^T + bias[N]   (M=4096, N=K=1024)
// mode 0/1/2: A = x input, write headed layout into g_q/g_k/g_v
// mode 3:     A = g_att,   write flat into Cflat (d_out)
// 128x128 tile, BK=8, 256 threads, 8x8 per-thread micro-tile.
// ---------------------------------------------------------------------------
__global__ __launch_bounds__(256, 2)
void sgemm_nt(const float* __restrict__ Ain, const float* __restrict__ W,
              const float* __restrict__ bias, float* __restrict__ Cflat, int mode)
{
    __shared__ float As[8][128];
    __shared__ float Bs[8][128];

    const float* A = (mode == 3) ? g_att : Ain;
    const int tid  = threadIdx.x;
    const int row0 = blockIdx.y * 128;
    const int col0 = blockIdx.x * 128;
    const int lr = tid >> 1;           // 0..127: row within tile for loads
    const int lc = (tid & 1) << 2;     // 0 or 4: k-offset for float4 load
    const int tr = (tid >> 4) << 3;    // micro-tile row base
    const int tc = (tid & 15) << 3;    // micro-tile col base

    float acc[8][8];
#pragma unroll
    for (int i = 0; i < 8; i++)
#pragma unroll
        for (int j = 0; j < 8; j++) acc[i][j] = 0.f;

    const float* Ap = A + (size_t)(row0 + lr) * EMB + lc;
    const float* Bp = W + (size_t)(col0 + lr) * EMB + lc;

    for (int k0 = 0; k0 < EMB; k0 += 8) {
        float4 a4 = *(const float4*)(Ap + k0);
        float4 b4 = *(const float4*)(Bp + k0);
        As[lc + 0][lr] = a4.x; As[lc + 1][lr] = a4.y;
        As[lc + 2][lr] = a4.z; As[lc + 3][lr] = a4.w;
        Bs[lc + 0][lr] = b4.x; Bs[lc + 1][lr] = b4.y;
        Bs[lc + 2][lr] = b4.z; Bs[lc + 3][lr] = b4.w;
        __syncthreads();
#pragma unroll
        for (int kk = 0; kk < 8; kk++) {
            float ar[8], br[8];
            *(float4*)(ar)     = *(const float4*)(&As[kk][tr]);
            *(float4*)(ar + 4) = *(const float4*)(&As[kk][tr + 4]);
            *(float4*)(br)     = *(const float4*)(&Bs[kk][tc]);
            *(float4*)(br + 4) = *(const float4*)(&Bs[kk][tc + 4]);
#pragma unroll
            for (int i = 0; i < 8; i++)
#pragma unroll
                for (int j = 0; j < 8; j++)
                    acc[i][j] += ar[i] * br[j];
        }
        __syncthreads();
    }

    if (mode == 3) {
#pragma unroll
        for (int i = 0; i < 8; i++) {
            float* cp = Cflat + (size_t)(row0 + tr + i) * EMB + col0 + tc;
#pragma unroll
            for (int j = 0; j < 8; j++)
                cp[j] = acc[i][j] + bias[col0 + tc + j];
        }
    } else {
        float* O = (mode == 0) ? g_q : (mode == 1) ? g_k : g_v;
#pragma unroll
        for (int i = 0; i < 8; i++) {
            int m = row0 + tr + i;
            int b = m >> 11;
            int s = m & (S_LEN - 1);
#pragma unroll
            for (int j = 0; j < 8; j++) {
                int n = col0 + tc + j;
                int h = n >> 6;
                int d = n & 63;
                O[(((size_t)(b * NHEAD + h) * S_LEN + s) << 6) + d] = acc[i][j] + bias[n];
            }
        }
    }
}

// ---------------------------------------------------------------------------
// Flash attention (causal), fp32. Block = one (b,h, q-tile of 64 rows).
// 256 threads: thread (r = tid/4, cq = tid%4) owns q-row r, 16-col slice cq.
// Streams K/V tiles of 64, online softmax, unnormalized O accumulation.
// Dynamic smem: Qs[64*64] Ks[64*64] Vs[64*64] Ps[64*68] (pad 68 kills the
// 8-way bank conflict on Ps[r][k] broadcast reads in the PV phase).
// ---------------------------------------------------------------------------
#define FLASH_SMEM (3 * 64 * 64 * 4 + 64 * 68 * 4)   // 66560 bytes

__global__ __launch_bounds__(256, 1)
void flash_kernel()
{
    extern __shared__ float sm[];
    float* Qs = sm;            // 64x64
    float* Ks = sm + 4096;     // 64x64
    float* Vs = sm + 8192;     // 64x64
    float* Ps = sm + 12288;    // 64x68

    const int qt  = blockIdx.x;   // 0..31 q tile
    const int bh  = blockIdx.y;   // 0..31 (b*16+h)
    const int tid = threadIdx.x;
    const int r   = tid >> 2;     // q row within tile 0..63
    const int cq  = tid & 3;      // column quarter 0..3

    const float* Qb = g_q + (size_t)bh * S_LEN * HDIM + (size_t)qt * 64 * HDIM;
    const float* Kb = g_k + (size_t)bh * S_LEN * HDIM;
    const float* Vb = g_v + (size_t)bh * S_LEN * HDIM;

    // load Q tile (contiguous 4096 floats)
#pragma unroll
    for (int it = 0; it < 4; it++)
        ((float4*)Qs)[tid + it * 256] = ((const float4*)Qb)[tid + it * 256];

    const int qg = qt * 64 + r;
    float mi = -1e30f, li = 0.f;
    float4 oa0 = make_float4(0.f, 0.f, 0.f, 0.f);
    float4 oa1 = oa0, oa2 = oa0, oa3 = oa0;
    const float4* Q4 = (const float4*)(Qs + r * 64);

    for (int kt = 0; kt <= qt; kt++) {
        __syncthreads();   // previous PV done before overwriting K/V/P
        const float4* ks = (const float4*)(Kb + (size_t)kt * 4096);
        const float4* vs = (const float4*)(Vb + (size_t)kt * 4096);
#pragma unroll
        for (int it = 0; it < 4; it++) {
            ((float4*)Ks)[tid + it * 256] = ks[tid + it * 256];
            ((float4*)Vs)[tid + it * 256] = vs[tid + it * 256];
        }
        __syncthreads();

        // S = Q K^T for 16 columns
        float sc[16];
#pragma unroll
        for (int j = 0; j < 16; j++) sc[j] = 0.f;
#pragma unroll
        for (int d4 = 0; d4 < 16; d4++) {
            float4 q4 = Q4[d4];
#pragma unroll
            for (int j = 0; j < 16; j++) {
                float4 k4 = ((const float4*)(Ks + (cq * 16 + j) * 64))[d4];
                sc[j] += q4.x * k4.x + q4.y * k4.y + q4.z * k4.z + q4.w * k4.w;
            }
        }

        // scale + causal mask + tile max
        float tmax = -1e30f;
        const int kbase = kt * 64 + cq * 16;
#pragma unroll
        for (int j = 0; j < 16; j++) {
            sc[j] *= 0.125f;                    // 1/sqrt(64)
            if (kbase + j > qg) sc[j] = -1e30f; // causal
            tmax = fmaxf(tmax, sc[j]);
        }
        tmax = fmaxf(tmax, __shfl_xor_sync(0xffffffffu, tmax, 1));
        tmax = fmaxf(tmax, __shfl_xor_sync(0xffffffffu, tmax, 2));
        float mnew = fmaxf(mi, tmax);

        float psum = 0.f;
#pragma unroll
        for (int j = 0; j < 16; j++) {
            sc[j] = __expf(sc[j] - mnew);
            psum += sc[j];
        }
        psum += __shfl_xor_sync(0xffffffffu, psum, 1);
        psum += __shfl_xor_sync(0xffffffffu, psum, 2);

        float alpha = __expf(mi - mnew);
        li = li * alpha + psum;
        mi = mnew;
        oa0.x *= alpha; oa0.y *= alpha; oa0.z *= alpha; oa0.w *= alpha;
        oa1.x *= alpha; oa1.y *= alpha; oa1.z *= alpha; oa1.w *= alpha;
        oa2.x *= alpha; oa2.y *= alpha; oa2.z *= alpha; oa2.w *= alpha;
        oa3.x *= alpha; oa3.y *= alpha; oa3.z *= alpha; oa3.w *= alpha;

        // stage P tile to smem (own cells only)
        float* pr = Ps + r * 68 + cq * 16;
        ((float4*)pr)[0] = make_float4(sc[0],  sc[1],  sc[2],  sc[3]);
        ((float4*)pr)[1] = make_float4(sc[4],  sc[5],  sc[6],  sc[7]);
        ((float4*)pr)[2] = make_float4(sc[8],  sc[9],  sc[10], sc[11]);
        ((float4*)pr)[3] = make_float4(sc[12], sc[13], sc[14], sc[15]);
        __syncthreads();

        // O += P V
#pragma unroll
        for (int k = 0; k < 64; k++) {
            float p = Ps[r * 68 + k];
            const float4* vr = (const float4*)(Vs + k * 64 + cq * 16);
            float4 v0 = vr[0], v1 = vr[1], v2 = vr[2], v3 = vr[3];
            oa0.x += p * v0.x; oa0.y += p * v0.y; oa0.z += p * v0.z; oa0.w += p * v0.w;
            oa1.x += p * v1.x; oa1.y += p * v1.y; oa1.z += p * v1.z; oa1.w += p * v1.w;
            oa2.x += p * v2.x; oa2.y += p * v2.y; oa2.z += p * v2.z; oa2.w += p * v2.w;
            oa3.x += p * v3.x; oa3.y += p * v3.y; oa3.z += p * v3.z; oa3.w += p * v3.w;
        }
    }

    // normalize + write [B,S,E] layout for output projection
    float inv = 1.f / li;
    int b = bh >> 4, h = bh & 15;
    float* op = g_att + ((size_t)(b * S_LEN + qg)) * EMB + h * 64 + cq * 16;
    oa0.x *= inv; oa0.y *= inv; oa0.z *= inv; oa0.w *= inv;
    oa1.x *= inv; oa1.y *= inv; oa1.z *= inv; oa1.w *= inv;
    oa2.x *= inv; oa2.y *= inv; oa2.z *= inv; oa2.w *= inv;
    oa3.x *= inv; oa3.y *= inv; oa3.z *= inv; oa3.w *= inv;
    ((float4*)op)[0] = oa0;
    ((float4*)op)[1] = oa1;
    ((float4*)op)[2] = oa2;
    ((float4*)op)[3] = oa3;
}

// ---------------------------------------------------------------------------
// inputs: 0=x 1=mask 2=Wq 3=bq 4=Wk 5=bk 6=Wv 7=bv 8=Wo 9=bo
// ---------------------------------------------------------------------------
extern "C" void kernel_launch(void* const* d_in, const int* in_sizes, int n_in,
                              void* d_out, int out_size)
{
    (void)in_sizes; (void)n_in; (void)out_size;
    const float* x  = (const float*)d_in[0];
    const float* Wq = (const float*)d_in[2];
    const float* bq = (const float*)d_in[3];
    const float* Wk = (const float*)d_in[4];
    const float* bk = (const float*)d_in[5];
    const float* Wv = (const float*)d_in[6];
    const float* bv = (const float*)d_in[7];
    const float* Wo = (const float*)d_in[8];
    const float* bo = (const float*)d_in[9];
    float* out = (float*)d_out;

    dim3 gg(EMB / 128, MROWS / 128);   // (8, 32)

    sgemm_nt<<<gg, 256>>>(x, Wq, bq, nullptr, 0);
    sgemm_nt<<<gg, 256>>>(x, Wk, bk, nullptr, 1);
    sgemm_nt<<<gg, 256>>>(x, Wv, bv, nullptr, 2);

    cudaFuncSetAttribute(flash_kernel,
                         cudaFuncAttributeMaxDynamicSharedMemorySize, FLASH_SMEM);
    flash_kernel<<<dim3(32, BATCH * NHEAD), 256, FLASH_SMEM>>>();

    sgemm_nt<<<gg, 256>>>(x, Wo, bo, out, 3);
}

// round 6
// speedup vs baseline: 2.7081x; 2.7081x over previous
#include <cuda_runtime.h>
#include <cuda_bf16.h>

#define S_LEN 2048
#define EMB   1024
#define NHEAD 16
#define HDIM  64
#define BATCH 2
#define MROWS 4096   // BATCH * S_LEN

// Scratch (allocation-free rule: __device__ globals)
__device__ __align__(16) float g_q[BATCH * NHEAD * S_LEN * HDIM];   // [B,H,S,D]
__device__ __align__(16) float g_k[BATCH * NHEAD * S_LEN * HDIM];
__device__ __align__(16) float g_v[BATCH * NHEAD * S_LEN * HDIM];
__device__ __align__(16) float g_att[BATCH * S_LEN * EMB];          // [B,S,E]

// ---------------------------------------------------------------------------
// GEMM: C[M,N] = A[M,K] * W[N,K]^T + bias[N]   (M=4096, N=K=1024)
// mode 0/1/2: A = x input, write headed layout into g_q/g_k/g_v
// mode 3:     A = g_att,   write flat into Cflat (d_out)
// 128x128 tile, BK=8, 256 threads, 8x8 per-thread micro-tile. (FMA-bound)
// ---------------------------------------------------------------------------
__global__ __launch_bounds__(256, 2)
void sgemm_nt(const float* __restrict__ Ain, const float* __restrict__ W,
              const float* __restrict__ bias, float* __restrict__ Cflat, int mode)
{
    __shared__ float As[8][128];
    __shared__ float Bs[8][128];

    const float* A = (mode == 3) ? g_att : Ain;
    const int tid  = threadIdx.x;
    const int row0 = blockIdx.y * 128;
    const int col0 = blockIdx.x * 128;
    const int lr = tid >> 1;           // 0..127: row within tile for loads
    const int lc = (tid & 1) << 2;     // 0 or 4: k-offset for float4 load
    const int tr = (tid >> 4) << 3;    // micro-tile row base
    const int tc = (tid & 15) << 3;    // micro-tile col base

    float acc[8][8];
#pragma unroll
    for (int i = 0; i < 8; i++)
#pragma unroll
        for (int j = 0; j < 8; j++) acc[i][j] = 0.f;

    const float* Ap = A + (size_t)(row0 + lr) * EMB + lc;
    const float* Bp = W + (size_t)(col0 + lr) * EMB + lc;

    for (int k0 = 0; k0 < EMB; k0 += 8) {
        float4 a4 = *(const float4*)(Ap + k0);
        float4 b4 = *(const float4*)(Bp + k0);
        As[lc + 0][lr] = a4.x; As[lc + 1][lr] = a4.y;
        As[lc + 2][lr] = a4.z; As[lc + 3][lr] = a4.w;
        Bs[lc + 0][lr] = b4.x; Bs[lc + 1][lr] = b4.y;
        Bs[lc + 2][lr] = b4.z; Bs[lc + 3][lr] = b4.w;
        __syncthreads();
#pragma unroll
        for (int kk = 0; kk < 8; kk++) {
            float ar[8], br[8];
            *(float4*)(ar)     = *(const float4*)(&As[kk][tr]);
            *(float4*)(ar + 4) = *(const float4*)(&As[kk][tr + 4]);
            *(float4*)(br)     = *(const float4*)(&Bs[kk][tc]);
            *(float4*)(br + 4) = *(const float4*)(&Bs[kk][tc + 4]);
#pragma unroll
            for (int i = 0; i < 8; i++)
#pragma unroll
                for (int j = 0; j < 8; j++)
                    acc[i][j] += ar[i] * br[j];
        }
        __syncthreads();
    }

    if (mode == 3) {
#pragma unroll
        for (int i = 0; i < 8; i++) {
            float* cp = Cflat + (size_t)(row0 + tr + i) * EMB + col0 + tc;
#pragma unroll
            for (int j = 0; j < 8; j++)
                cp[j] = acc[i][j] + bias[col0 + tc + j];
        }
    } else {
        float* O = (mode == 0) ? g_q : (mode == 1) ? g_k : g_v;
#pragma unroll
        for (int i = 0; i < 8; i++) {
            int m = row0 + tr + i;
            int b = m >> 11;
            int s = m & (S_LEN - 1);
#pragma unroll
            for (int j = 0; j < 8; j++) {
                int n = col0 + tc + j;
                int h = n >> 6;
                int d = n & 63;
                O[(((size_t)(b * NHEAD + h) * S_LEN + s) << 6) + d] = acc[i][j] + bias[n];
            }
        }
    }
}

// ---------------------------------------------------------------------------
// Flash attention (causal), fp32, register-tiled.
// Block = (b,h, q-tile of 64). 256 threads as 16x16 grid; thread (tr,ti)
// owns a 4x4 micro-tile: q-rows 4*tr..+3, cols 4*ti..+3.
// Q,K staged d-major (Qt[d][r], Kt[d][c]) so the S phase is an outer-product
// GEMM: per d-step 2 conflict-free float4 LDS feed 16 FMAs.
// P row-major (broadcast float4 loads), V s-major. Rows padded to 68 floats.
// ---------------------------------------------------------------------------
#define FPAD 68
#define FLASH_SMEM (4 * 64 * FPAD * 4)   // 69632 bytes

__global__ __launch_bounds__(256, 2)
void flash_kernel()
{
    extern __shared__ float sm[];
    float* Qt = sm;                 // [64][FPAD]  Qt[d][r]
    float* Kt = sm + 64 * FPAD;     // [64][FPAD]  Kt[d][c]
    float* Vs = sm + 2 * 64 * FPAD; // [64][FPAD]  Vs[k][d]
    float* Ps = sm + 3 * 64 * FPAD; // [64][FPAD]  Ps[r][k]

    const int qt  = 31 - blockIdx.x;   // heavy tiles first (wave balance)
    const int bh  = blockIdx.y;        // 0..31 (b*16+h)
    const int tid = threadIdx.x;
    const int tr  = tid >> 4;          // 0..15 row group
    const int ti  = tid & 15;          // 0..15 col group

    const float* Qb = g_q + (size_t)bh * S_LEN * HDIM + (size_t)qt * 64 * HDIM;
    const float* Kb = g_k + (size_t)bh * S_LEN * HDIM;
    const float* Vb = g_v + (size_t)bh * S_LEN * HDIM;

    // Load Q tile, transpose into Qt[d][r]
#pragma unroll
    for (int it = 0; it < 4; it++) {
        int r = tr + 16 * it;
        float4 q4 = ((const float4*)(Qb + (size_t)r * HDIM))[ti];
        Qt[(4 * ti + 0) * FPAD + r] = q4.x;
        Qt[(4 * ti + 1) * FPAD + r] = q4.y;
        Qt[(4 * ti + 2) * FPAD + r] = q4.z;
        Qt[(4 * ti + 3) * FPAD + r] = q4.w;
    }

    float o[4][4];
    float mi[4], li[4];
#pragma unroll
    for (int i = 0; i < 4; i++) {
        mi[i] = -1e30f; li[i] = 0.f;
#pragma unroll
        for (int j = 0; j < 4; j++) o[i][j] = 0.f;
    }

    for (int kt = 0; kt <= qt; kt++) {
        __syncthreads();   // prior PV / smem use complete
        // load K (transposed) and V tiles
#pragma unroll
        for (int it = 0; it < 4; it++) {
            int s = tr + 16 * it;
            const float* krow = Kb + (size_t)(kt * 64 + s) * HDIM;
            float4 k4 = ((const float4*)krow)[ti];
            Kt[(4 * ti + 0) * FPAD + s] = k4.x;
            Kt[(4 * ti + 1) * FPAD + s] = k4.y;
            Kt[(4 * ti + 2) * FPAD + s] = k4.z;
            Kt[(4 * ti + 3) * FPAD + s] = k4.w;
            const float* vrow = Vb + (size_t)(kt * 64 + s) * HDIM;
            float4 v4 = ((const float4*)vrow)[ti];
            *(float4*)&Vs[s * FPAD + 4 * ti] = v4;
        }
        __syncthreads();

        // S = Q K^T : outer-product over d
        float sa[4][4];
#pragma unroll
        for (int i = 0; i < 4; i++)
#pragma unroll
            for (int j = 0; j < 4; j++) sa[i][j] = 0.f;

#pragma unroll 8
        for (int d = 0; d < 64; d++) {
            float4 q = *(const float4*)&Qt[d * FPAD + 4 * tr];
            float4 k = *(const float4*)&Kt[d * FPAD + 4 * ti];
            sa[0][0] += q.x * k.x; sa[0][1] += q.x * k.y; sa[0][2] += q.x * k.z; sa[0][3] += q.x * k.w;
            sa[1][0] += q.y * k.x; sa[1][1] += q.y * k.y; sa[1][2] += q.y * k.z; sa[1][3] += q.y * k.w;
            sa[2][0] += q.z * k.x; sa[2][1] += q.z * k.y; sa[2][2] += q.z * k.z; sa[2][3] += q.z * k.w;
            sa[3][0] += q.w * k.x; sa[3][1] += q.w * k.y; sa[3][2] += q.w * k.z; sa[3][3] += q.w * k.w;
        }

        // scale + causal mask (diagonal tile only)
        if (kt == qt) {
#pragma unroll
            for (int i = 0; i < 4; i++)
#pragma unroll
                for (int j = 0; j < 4; j++)
                    sa[i][j] = (4 * ti + j > 4 * tr + i) ? -1e30f : sa[i][j] * 0.125f;
        } else {
#pragma unroll
            for (int i = 0; i < 4; i++)
#pragma unroll
                for (int j = 0; j < 4; j++) sa[i][j] *= 0.125f;
        }

        // online softmax (rows owned by 16 lanes sharing tr; shuffle over ti)
        float rmax[4], rsum[4];
#pragma unroll
        for (int i = 0; i < 4; i++) {
            rmax[i] = fmaxf(fmaxf(sa[i][0], sa[i][1]), fmaxf(sa[i][2], sa[i][3]));
#pragma unroll
            for (int off = 1; off < 16; off <<= 1)
                rmax[i] = fmaxf(rmax[i], __shfl_xor_sync(0xffffffffu, rmax[i], off));
        }
#pragma unroll
        for (int i = 0; i < 4; i++) {
            float mnew = fmaxf(mi[i], rmax[i]);
            float s0 = __expf(sa[i][0] - mnew);
            float s1 = __expf(sa[i][1] - mnew);
            float s2 = __expf(sa[i][2] - mnew);
            float s3 = __expf(sa[i][3] - mnew);
            sa[i][0] = s0; sa[i][1] = s1; sa[i][2] = s2; sa[i][3] = s3;
            rsum[i] = s0 + s1 + s2 + s3;
#pragma unroll
            for (int off = 1; off < 16; off <<= 1)
                rsum[i] += __shfl_xor_sync(0xffffffffu, rsum[i], off);
            float alpha = __expf(mi[i] - mnew);
            li[i] = li[i] * alpha + rsum[i];
            mi[i] = mnew;
            o[i][0] *= alpha; o[i][1] *= alpha; o[i][2] *= alpha; o[i][3] *= alpha;
        }

        // stage P (row-major)
#pragma unroll
        for (int i = 0; i < 4; i++)
            *(float4*)&Ps[(4 * tr + i) * FPAD + 4 * ti] =
                make_float4(sa[i][0], sa[i][1], sa[i][2], sa[i][3]);
        __syncthreads();

        // O += P V : register-tiled, broadcast P loads + contiguous V loads
#pragma unroll 4
        for (int k4 = 0; k4 < 16; k4++) {
            float4 p0 = *(const float4*)&Ps[(4 * tr + 0) * FPAD + 4 * k4];
            float4 p1 = *(const float4*)&Ps[(4 * tr + 1) * FPAD + 4 * k4];
            float4 p2 = *(const float4*)&Ps[(4 * tr + 2) * FPAD + 4 * k4];
            float4 p3 = *(const float4*)&Ps[(4 * tr + 3) * FPAD + 4 * k4];
            float pm[4][4] = {{p0.x, p0.y, p0.z, p0.w},
                              {p1.x, p1.y, p1.z, p1.w},
                              {p2.x, p2.y, p2.z, p2.w},
                              {p3.x, p3.y, p3.z, p3.w}};
#pragma unroll
            for (int kk = 0; kk < 4; kk++) {
                float4 v = *(const float4*)&Vs[(4 * k4 + kk) * FPAD + 4 * ti];
#pragma unroll
                for (int i = 0; i < 4; i++) {
                    o[i][0] += pm[i][kk] * v.x;
                    o[i][1] += pm[i][kk] * v.y;
                    o[i][2] += pm[i][kk] * v.z;
                    o[i][3] += pm[i][kk] * v.w;
                }
            }
        }
    }

    // normalize + write [B,S,E] layout for output projection
    int b = bh >> 4, h = bh & 15;
#pragma unroll
    for (int i = 0; i < 4; i++) {
        float inv = 1.f / li[i];
        int qg = qt * 64 + 4 * tr + i;
        float* op = g_att + ((size_t)(b * S_LEN + qg)) * EMB + h * 64 + 4 * ti;
        *(float4*)op = make_float4(o[i][0] * inv, o[i][1] * inv,
                                   o[i][2] * inv, o[i][3] * inv);
    }
}

// ---------------------------------------------------------------------------
// inputs: 0=x 1=mask 2=Wq 3=bq 4=Wk 5=bk 6=Wv 7=bv 8=Wo 9=bo
// ---------------------------------------------------------------------------
extern "C" void kernel_launch(void* const* d_in, const int* in_sizes, int n_in,
                              void* d_out, int out_size)
{
    (void)in_sizes; (void)n_in; (void)out_size;
    const float* x  = (const float*)d_in[0];
    const float* Wq = (const float*)d_in[2];
    const float* bq = (const float*)d_in[3];
    const float* Wk = (const float*)d_in[4];
    const float* bk = (const float*)d_in[5];
    const float* Wv = (const float*)d_in[6];
    const float* bv = (const float*)d_in[7];
    const float* Wo = (const float*)d_in[8];
    const float* bo = (const float*)d_in[9];
    float* out = (float*)d_out;

    dim3 gg(EMB / 128, MROWS / 128);   // (8, 32)

    sgemm_nt<<<gg, 256>>>(x, Wq, bq, nullptr, 0);
    sgemm_nt<<<gg, 256>>>(x, Wk, bk, nullptr, 1);
    sgemm_nt<<<gg, 256>>>(x, Wv, bv, nullptr, 2);

    cudaFuncSetAttribute(flash_kernel,
                         cudaFuncAttributeMaxDynamicSharedMemorySize, FLASH_SMEM);
    flash_kernel<<<dim3(32, BATCH * NHEAD), 256, FLASH_SMEM>>>();

    sgemm_nt<<<gg, 256>>>(x, Wo, bo, out, 3);
}

// round 10
// speedup vs baseline: 5.0476x; 1.8639x over previous
#include <cuda_runtime.h>
#include <cuda_bf16.h>
#include <cstdint>

#define S_LEN 2048
#define EMB   1024
#define NHEAD 16
#define HDIM  64
#define BATCH 2
#define MROWS 4096   // BATCH * S_LEN

// Scratch (allocation-free rule: __device__ globals)
__device__ __align__(16) float g_q[BATCH * NHEAD * S_LEN * HDIM];   // [B,H,S,D]
__device__ __align__(16) float g_k[BATCH * NHEAD * S_LEN * HDIM];
__device__ __align__(16) float g_v[BATCH * NHEAD * S_LEN * HDIM];
__device__ __align__(16) float g_att[BATCH * S_LEN * EMB];          // [B,S,E]

// ---------------------------------------------------------------------------
// 3xTF32 helpers
// ---------------------------------------------------------------------------
__device__ __forceinline__ void tf32_split(float x, uint32_t& hi, uint32_t& lo)
{
    uint32_t h;
    asm("cvt.rna.tf32.f32 %0, %1;" : "=r"(h) : "f"(x));
    float r = x - __uint_as_float(h);   // exact (exponents close)
    uint32_t l;
    asm("cvt.rna.tf32.f32 %0, %1;" : "=r"(l) : "f"(r));
    hi = h; lo = l;
}

__device__ __forceinline__ void mma_tf32(float4& d, const uint32_t a[4],
                                         uint32_t b0, uint32_t b1)
{
    asm volatile(
        "mma.sync.aligned.m16n8k8.row.col.f32.tf32.tf32.f32 "
        "{%0,%1,%2,%3}, {%4,%5,%6,%7}, {%8,%9}, {%0,%1,%2,%3};\n"
        : "+f"(d.x), "+f"(d.y), "+f"(d.z), "+f"(d.w)
        : "r"(a[0]), "r"(a[1]), "r"(a[2]), "r"(a[3]), "r"(b0), "r"(b1));
}

// ---------------------------------------------------------------------------
// GEMM: C[M,N] = A[M,K] * W[N,K]^T + bias[N]   (M=4096, N=K=1024)
// 3xTF32 tensor-core version. 128x128 tile, BK=16, 256 threads (8 warps 2x4),
// each warp owns 64x32 = 4 m-frags (m16) x 4 n-frags (n8).
// smem: As[128][20], Bs[128][20] — [row][k], pad 20 is conflict-free for the
// m16n8k8 fragment pattern (row strides {0,20,8,28,16,4,24,12} mod 32 + 0..3).
// mode 0/1/2: A = x, headed output to g_q/g_k/g_v; mode 3: A = g_att, flat.
// ---------------------------------------------------------------------------
__global__ __launch_bounds__(256, 2)
void sgemm_tf32(const float* __restrict__ Ain, const float* __restrict__ W,
                const float* __restrict__ bias, float* __restrict__ Cflat, int mode)
{
    __shared__ float As[128][20];
    __shared__ float Bs[128][20];

    const float* A = (mode == 3) ? g_att : Ain;
    const int tid  = threadIdx.x;
    const int row0 = blockIdx.y * 128;
    const int col0 = blockIdx.x * 128;
    const int lane = tid & 31;
    const int wid  = tid >> 5;
    const int g    = lane >> 2;     // group id 0..7
    const int t4   = lane & 3;      // thread-in-group 0..3
    const int m0   = (wid >> 2) * 64;   // warp M base within tile
    const int n0   = (wid & 3) * 32;    // warp N base within tile

    float4 acc[4][4];
#pragma unroll
    for (int f = 0; f < 4; f++)
#pragma unroll
        for (int j = 0; j < 4; j++)
            acc[f][j] = make_float4(0.f, 0.f, 0.f, 0.f);

    for (int kb = 0; kb < EMB; kb += 16) {
        // stage A and W tiles: 512 float4 each, 2 per thread
#pragma unroll
        for (int i = 0; i < 2; i++) {
            int id = tid + 256 * i;
            int r  = id >> 2;
            int kq = (id & 3) << 2;
            *(float4*)&As[r][kq] = *(const float4*)(A + (size_t)(row0 + r) * EMB + kb + kq);
            *(float4*)&Bs[r][kq] = *(const float4*)(W + (size_t)(col0 + r) * EMB + kb + kq);
        }
        __syncthreads();

#pragma unroll
        for (int kk = 0; kk < 16; kk += 8) {
            // A fragments (hi/lo) for 4 m-frags
            uint32_t ah[4][4], al[4][4];
#pragma unroll
            for (int f = 0; f < 4; f++) {
                tf32_split(As[m0 + 16 * f + g    ][kk + t4    ], ah[f][0], al[f][0]);
                tf32_split(As[m0 + 16 * f + g + 8][kk + t4    ], ah[f][1], al[f][1]);
                tf32_split(As[m0 + 16 * f + g    ][kk + t4 + 4], ah[f][2], al[f][2]);
                tf32_split(As[m0 + 16 * f + g + 8][kk + t4 + 4], ah[f][3], al[f][3]);
            }
#pragma unroll
            for (int j = 0; j < 4; j++) {
                uint32_t bh0, bl0, bh1, bl1;
                tf32_split(Bs[n0 + 8 * j + g][kk + t4    ], bh0, bl0);
                tf32_split(Bs[n0 + 8 * j + g][kk + t4 + 4], bh1, bl1);
#pragma unroll
                for (int f = 0; f < 4; f++) {
                    mma_tf32(acc[f][j], ah[f], bh0, bh1);   // hi*hi
                    mma_tf32(acc[f][j], ah[f], bl0, bl1);   // hi*lo
                    mma_tf32(acc[f][j], al[f], bh0, bh1);   // lo*hi
                }
            }
        }
        __syncthreads();
    }

    // epilogue: c0,c1 at (row, 2*t4 + {0,1}); c2,c3 at row+8
    if (mode == 3) {
#pragma unroll
        for (int f = 0; f < 4; f++) {
            int r1 = row0 + m0 + 16 * f + g;
#pragma unroll
            for (int j = 0; j < 4; j++) {
                int c  = col0 + n0 + 8 * j + 2 * t4;
                float bx = bias[c], by = bias[c + 1];
                *(float2*)&Cflat[(size_t)r1 * EMB + c] =
                    make_float2(acc[f][j].x + bx, acc[f][j].y + by);
                *(float2*)&Cflat[(size_t)(r1 + 8) * EMB + c] =
                    make_float2(acc[f][j].z + bx, acc[f][j].w + by);
            }
        }
    } else {
        float* O = (mode == 0) ? g_q : (mode == 1) ? g_k : g_v;
#pragma unroll
        for (int f = 0; f < 4; f++) {
#pragma unroll
            for (int j = 0; j < 4; j++) {
                int c = col0 + n0 + 8 * j + 2 * t4;
                int h = c >> 6, d = c & 63;
                float bx = bias[c], by = bias[c + 1];
#pragma unroll
                for (int rr = 0; rr < 2; rr++) {
                    int m = row0 + m0 + 16 * f + g + 8 * rr;
                    int b = m >> 11;
                    int s = m & (S_LEN - 1);
                    size_t base = (((size_t)(b * NHEAD + h) * S_LEN + s) << 6) + d;
                    float vx = (rr == 0) ? acc[f][j].x : acc[f][j].z;
                    float vy = (rr == 0) ? acc[f][j].y : acc[f][j].w;
                    *(float2*)&O[base] = make_float2(vx + bx, vy + by);
                }
            }
        }
    }
}

// ---------------------------------------------------------------------------
// Flash attention (causal), fp32, register-tiled (unchanged from R6-best).
// ---------------------------------------------------------------------------
#define FPAD 68
#define FLASH_SMEM (4 * 64 * FPAD * 4)   // 69632 bytes

__global__ __launch_bounds__(256, 2)
void flash_kernel()
{
    extern __shared__ float sm[];
    float* Qt = sm;                 // [64][FPAD]  Qt[d][r]
    float* Kt = sm + 64 * FPAD;     // [64][FPAD]  Kt[d][c]
    float* Vs = sm + 2 * 64 * FPAD; // [64][FPAD]  Vs[k][d]
    float* Ps = sm + 3 * 64 * FPAD; // [64][FPAD]  Ps[r][k]

    const int qt  = 31 - blockIdx.x;   // heavy tiles first (wave balance)
    const int bh  = blockIdx.y;        // 0..31 (b*16+h)
    const int tid = threadIdx.x;
    const int tr  = tid >> 4;          // 0..15 row group
    const int ti  = tid & 15;          // 0..15 col group

    const float* Qb = g_q + (size_t)bh * S_LEN * HDIM + (size_t)qt * 64 * HDIM;
    const float* Kb = g_k + (size_t)bh * S_LEN * HDIM;
    const float* Vb = g_v + (size_t)bh * S_LEN * HDIM;

#pragma unroll
    for (int it = 0; it < 4; it++) {
        int r = tr + 16 * it;
        float4 q4 = ((const float4*)(Qb + (size_t)r * HDIM))[ti];
        Qt[(4 * ti + 0) * FPAD + r] = q4.x;
        Qt[(4 * ti + 1) * FPAD + r] = q4.y;
        Qt[(4 * ti + 2) * FPAD + r] = q4.z;
        Qt[(4 * ti + 3) * FPAD + r] = q4.w;
    }

    float o[4][4];
    float mi[4], li[4];
#pragma unroll
    for (int i = 0; i < 4; i++) {
        mi[i] = -1e30f; li[i] = 0.f;
#pragma unroll
        for (int j = 0; j < 4; j++) o[i][j] = 0.f;
    }

    for (int kt = 0; kt <= qt; kt++) {
        __syncthreads();
#pragma unroll
        for (int it = 0; it < 4; it++) {
            int s = tr + 16 * it;
            const float* krow = Kb + (size_t)(kt * 64 + s) * HDIM;
            float4 k4 = ((const float4*)krow)[ti];
            Kt[(4 * ti + 0) * FPAD + s] = k4.x;
            Kt[(4 * ti + 1) * FPAD + s] = k4.y;
            Kt[(4 * ti + 2) * FPAD + s] = k4.z;
            Kt[(4 * ti + 3) * FPAD + s] = k4.w;
            const float* vrow = Vb + (size_t)(kt * 64 + s) * HDIM;
            float4 v4 = ((const float4*)vrow)[ti];
            *(float4*)&Vs[s * FPAD + 4 * ti] = v4;
        }
        __syncthreads();

        float sa[4][4];
#pragma unroll
        for (int i = 0; i < 4; i++)
#pragma unroll
            for (int j = 0; j < 4; j++) sa[i][j] = 0.f;

#pragma unroll 8
        for (int d = 0; d < 64; d++) {
            float4 q = *(const float4*)&Qt[d * FPAD + 4 * tr];
            float4 k = *(const float4*)&Kt[d * FPAD + 4 * ti];
            sa[0][0] += q.x * k.x; sa[0][1] += q.x * k.y; sa[0][2] += q.x * k.z; sa[0][3] += q.x * k.w;
            sa[1][0] += q.y * k.x; sa[1][1] += q.y * k.y; sa[1][2] += q.y * k.z; sa[1][3] += q.y * k.w;
            sa[2][0] += q.z * k.x; sa[2][1] += q.z * k.y; sa[2][2] += q.z * k.z; sa[2][3] += q.z * k.w;
            sa[3][0] += q.w * k.x; sa[3][1] += q.w * k.y; sa[3][2] += q.w * k.z; sa[3][3] += q.w * k.w;
        }

        if (kt == qt) {
#pragma unroll
            for (int i = 0; i < 4; i++)
#pragma unroll
                for (int j = 0; j < 4; j++)
                    sa[i][j] = (4 * ti + j > 4 * tr + i) ? -1e30f : sa[i][j] * 0.125f;
        } else {
#pragma unroll
            for (int i = 0; i < 4; i++)
#pragma unroll
                for (int j = 0; j < 4; j++) sa[i][j] *= 0.125f;
        }

        float rmax[4], rsum[4];
#pragma unroll
        for (int i = 0; i < 4; i++) {
            rmax[i] = fmaxf(fmaxf(sa[i][0], sa[i][1]), fmaxf(sa[i][2], sa[i][3]));
#pragma unroll
            for (int off = 1; off < 16; off <<= 1)
                rmax[i] = fmaxf(rmax[i], __shfl_xor_sync(0xffffffffu, rmax[i], off));
        }
#pragma unroll
        for (int i = 0; i < 4; i++) {
            float mnew = fmaxf(mi[i], rmax[i]);
            float s0 = __expf(sa[i][0] - mnew);
            float s1 = __expf(sa[i][1] - mnew);
            float s2 = __expf(sa[i][2] - mnew);
            float s3 = __expf(sa[i][3] - mnew);
            sa[i][0] = s0; sa[i][1] = s1; sa[i][2] = s2; sa[i][3] = s3;
            rsum[i] = s0 + s1 + s2 + s3;
#pragma unroll
            for (int off = 1; off < 16; off <<= 1)
                rsum[i] += __shfl_xor_sync(0xffffffffu, rsum[i], off);
            float alpha = __expf(mi[i] - mnew);
            li[i] = li[i] * alpha + rsum[i];
            mi[i] = mnew;
            o[i][0] *= alpha; o[i][1] *= alpha; o[i][2] *= alpha; o[i][3] *= alpha;
        }

#pragma unroll
        for (int i = 0; i < 4; i++)
            *(float4*)&Ps[(4 * tr + i) * FPAD + 4 * ti] =
                make_float4(sa[i][0], sa[i][1], sa[i][2], sa[i][3]);
        __syncthreads();

#pragma unroll 4
        for (int k4 = 0; k4 < 16; k4++) {
            float4 p0 = *(const float4*)&Ps[(4 * tr + 0) * FPAD + 4 * k4];
            float4 p1 = *(const float4*)&Ps[(4 * tr + 1) * FPAD + 4 * k4];
            float4 p2 = *(const float4*)&Ps[(4 * tr + 2) * FPAD + 4 * k4];
            float4 p3 = *(const float4*)&Ps[(4 * tr + 3) * FPAD + 4 * k4];
            float pm[4][4] = {{p0.x, p0.y, p0.z, p0.w},
                              {p1.x, p1.y, p1.z, p1.w},
                              {p2.x, p2.y, p2.z, p2.w},
                              {p3.x, p3.y, p3.z, p3.w}};
#pragma unroll
            for (int kk = 0; kk < 4; kk++) {
                float4 v = *(const float4*)&Vs[(4 * k4 + kk) * FPAD + 4 * ti];
#pragma unroll
                for (int i = 0; i < 4; i++) {
                    o[i][0] += pm[i][kk] * v.x;
                    o[i][1] += pm[i][kk] * v.y;
                    o[i][2] += pm[i][kk] * v.z;
                    o[i][3] += pm[i][kk] * v.w;
                }
            }
        }
    }

    int b = bh >> 4, h = bh & 15;
#pragma unroll
    for (int i = 0; i < 4; i++) {
        float inv = 1.f / li[i];
        int qg = qt * 64 + 4 * tr + i;
        float* op = g_att + ((size_t)(b * S_LEN + qg)) * EMB + h * 64 + 4 * ti;
        *(float4*)op = make_float4(o[i][0] * inv, o[i][1] * inv,
                                   o[i][2] * inv, o[i][3] * inv);
    }
}

// ---------------------------------------------------------------------------
// inputs: 0=x 1=mask 2=Wq 3=bq 4=Wk 5=bk 6=Wv 7=bv 8=Wo 9=bo
// ---------------------------------------------------------------------------
extern "C" void kernel_launch(void* const* d_in, const int* in_sizes, int n_in,
                              void* d_out, int out_size)
{
    (void)in_sizes; (void)n_in; (void)out_size;
    const float* x  = (const float*)d_in[0];
    const float* Wq = (const float*)d_in[2];
    const float* bq = (const float*)d_in[3];
    const float* Wk = (const float*)d_in[4];
    const float* bk = (const float*)d_in[5];
    const float* Wv = (const float*)d_in[6];
    const float* bv = (const float*)d_in[7];
    const float* Wo = (const float*)d_in[8];
    const float* bo = (const float*)d_in[9];
    float* out = (float*)d_out;

    dim3 gg(EMB / 128, MROWS / 128);   // (8, 32)

    sgemm_tf32<<<gg, 256>>>(x, Wq, bq, nullptr, 0);
    sgemm_tf32<<<gg, 256>>>(x, Wk, bk, nullptr, 1);
    sgemm_tf32<<<gg, 256>>>(x, Wv, bv, nullptr, 2);

    cudaFuncSetAttribute(flash_kernel,
                         cudaFuncAttributeMaxDynamicSharedMemorySize, FLASH_SMEM);
    flash_kernel<<<dim3(32, BATCH * NHEAD), 256, FLASH_SMEM>>>();

    sgemm_tf32<<<gg, 256>>>(x, Wo, bo, out, 3);
}

// round 11
// speedup vs baseline: 6.5971x; 1.3070x over previous
#include <cuda_runtime.h>
#include <cuda_bf16.h>
#include <cstdint>

#define S_LEN 2048
#define EMB   1024
#define NHEAD 16
#define HDIM  64
#define BATCH 2
#define MROWS 4096   // BATCH * S_LEN

// Scratch (allocation-free rule: __device__ globals)
__device__ __align__(16) float g_q [BATCH * NHEAD * S_LEN * HDIM];  // [B,H,S,D]
__device__ __align__(16) float g_k [BATCH * NHEAD * S_LEN * HDIM];  // [B,H,S,D]
__device__ __align__(16) float g_vt[BATCH * NHEAD * HDIM * S_LEN];  // [B,H,D,S] tf32-rounded
__device__ __align__(16) float g_att[BATCH * S_LEN * EMB];          // [B,S,E]

// ---------------------------------------------------------------------------
// 3xTF32 helpers
// ---------------------------------------------------------------------------
__device__ __forceinline__ void tf32_split(float x, uint32_t& hi, uint32_t& lo)
{
    uint32_t h;
    asm("cvt.rna.tf32.f32 %0, %1;" : "=r"(h) : "f"(x));
    float r = x - __uint_as_float(h);   // exact
    uint32_t l;
    asm("cvt.rna.tf32.f32 %0, %1;" : "=r"(l) : "f"(r));
    hi = h; lo = l;
}

__device__ __forceinline__ float tf32r(float x)
{
    uint32_t r;
    asm("cvt.rna.tf32.f32 %0, %1;" : "=r"(r) : "f"(x));
    return __uint_as_float(r);
}

__device__ __forceinline__ void mma_tf32(float4& d, const uint32_t a[4],
                                         uint32_t b0, uint32_t b1)
{
    asm volatile(
        "mma.sync.aligned.m16n8k8.row.col.f32.tf32.tf32.f32 "
        "{%0,%1,%2,%3}, {%4,%5,%6,%7}, {%8,%9}, {%0,%1,%2,%3};\n"
        : "+f"(d.x), "+f"(d.y), "+f"(d.z), "+f"(d.w)
        : "r"(a[0]), "r"(a[1]), "r"(a[2]), "r"(a[3]), "r"(b0), "r"(b1));
}

__device__ __forceinline__ void split4(float4 v, float4& hi, float4& lo)
{
    uint32_t h, l;
    tf32_split(v.x, h, l); hi.x = __uint_as_float(h); lo.x = __uint_as_float(l);
    tf32_split(v.y, h, l); hi.y = __uint_as_float(h); lo.y = __uint_as_float(l);
    tf32_split(v.z, h, l); hi.z = __uint_as_float(h); lo.z = __uint_as_float(l);
    tf32_split(v.w, h, l); hi.w = __uint_as_float(h); lo.w = __uint_as_float(l);
}

#define F2U(x) __float_as_uint(x)

// ---------------------------------------------------------------------------
// GEMM: C[M,N] = A[M,K] * W[N,K]^T + bias[N]   (M=4096, N=K=1024)
// 3xTF32, pre-split hi/lo staging (no splits in the inner loop).
// mode_sel < 0 : fused QKV, mode = blockIdx.z (0=Q,1=K,2=V); A = x input.
//   mode 0/1 -> headed [B,H,S,D] into g_q/g_k
//   mode 2   -> transposed+tf32-rounded [B,H,D,S] into g_vt
// mode_sel == 3: A = g_att, flat output into Cflat (+bias) using W0/b0.
// ---------------------------------------------------------------------------
__global__ __launch_bounds__(256, 2)
void sgemm_tf32(const float* __restrict__ Ain,
                const float* __restrict__ W0, const float* __restrict__ W1,
                const float* __restrict__ W2,
                const float* __restrict__ b0p, const float* __restrict__ b1p,
                const float* __restrict__ b2p,
                float* __restrict__ Cflat, int mode_sel)
{
    __shared__ float Ah[128][20], Al[128][20];
    __shared__ float Bh[128][20], Bl[128][20];

    const int mode = (mode_sel < 0) ? (int)blockIdx.z : mode_sel;
    const float* W    = (mode == 1) ? W1 : (mode == 2) ? W2 : W0;
    const float* bias = (mode == 1) ? b1p : (mode == 2) ? b2p : b0p;
    const float* A    = (mode == 3) ? g_att : Ain;

    const int tid  = threadIdx.x;
    const int row0 = blockIdx.y * 128;
    const int col0 = blockIdx.x * 128;
    const int lane = tid & 31;
    const int wid  = tid >> 5;
    const int g    = lane >> 2;
    const int t4   = lane & 3;
    const int m0   = (wid >> 2) * 64;
    const int n0   = (wid & 3) * 32;

    float4 acc[4][4];
#pragma unroll
    for (int f = 0; f < 4; f++)
#pragma unroll
        for (int j = 0; j < 4; j++)
            acc[f][j] = make_float4(0.f, 0.f, 0.f, 0.f);

    for (int kb = 0; kb < EMB; kb += 16) {
#pragma unroll
        for (int i = 0; i < 2; i++) {
            int id = tid + 256 * i;
            int r  = id >> 2;
            int kq = (id & 3) << 2;
            float4 a4 = *(const float4*)(A + (size_t)(row0 + r) * EMB + kb + kq);
            float4 w4 = *(const float4*)(W + (size_t)(col0 + r) * EMB + kb + kq);
            float4 hi, lo;
            split4(a4, hi, lo);
            *(float4*)&Ah[r][kq] = hi; *(float4*)&Al[r][kq] = lo;
            split4(w4, hi, lo);
            *(float4*)&Bh[r][kq] = hi; *(float4*)&Bl[r][kq] = lo;
        }
        __syncthreads();

#pragma unroll
        for (int kk = 0; kk < 16; kk += 8) {
            uint32_t ah[4][4], al[4][4];
#pragma unroll
            for (int f = 0; f < 4; f++) {
                ah[f][0] = F2U(Ah[m0 + 16 * f + g    ][kk + t4    ]);
                ah[f][1] = F2U(Ah[m0 + 16 * f + g + 8][kk + t4    ]);
                ah[f][2] = F2U(Ah[m0 + 16 * f + g    ][kk + t4 + 4]);
                ah[f][3] = F2U(Ah[m0 + 16 * f + g + 8][kk + t4 + 4]);
                al[f][0] = F2U(Al[m0 + 16 * f + g    ][kk + t4    ]);
                al[f][1] = F2U(Al[m0 + 16 * f + g + 8][kk + t4    ]);
                al[f][2] = F2U(Al[m0 + 16 * f + g    ][kk + t4 + 4]);
                al[f][3] = F2U(Al[m0 + 16 * f + g + 8][kk + t4 + 4]);
            }
#pragma unroll
            for (int j = 0; j < 4; j++) {
                uint32_t bh0 = F2U(Bh[n0 + 8 * j + g][kk + t4    ]);
                uint32_t bh1 = F2U(Bh[n0 + 8 * j + g][kk + t4 + 4]);
                uint32_t bl0 = F2U(Bl[n0 + 8 * j + g][kk + t4    ]);
                uint32_t bl1 = F2U(Bl[n0 + 8 * j + g][kk + t4 + 4]);
#pragma unroll
                for (int f = 0; f < 4; f++) {
                    mma_tf32(acc[f][j], ah[f], bh0, bh1);
                    mma_tf32(acc[f][j], ah[f], bl0, bl1);
                    mma_tf32(acc[f][j], al[f], bh0, bh1);
                }
            }
        }
        __syncthreads();
    }

    if (mode == 3) {
#pragma unroll
        for (int f = 0; f < 4; f++) {
            int r1 = row0 + m0 + 16 * f + g;
#pragma unroll
            for (int j = 0; j < 4; j++) {
                int c  = col0 + n0 + 8 * j + 2 * t4;
                float bx = bias[c], by = bias[c + 1];
                *(float2*)&Cflat[(size_t)r1 * EMB + c] =
                    make_float2(acc[f][j].x + bx, acc[f][j].y + by);
                *(float2*)&Cflat[(size_t)(r1 + 8) * EMB + c] =
                    make_float2(acc[f][j].z + bx, acc[f][j].w + by);
            }
        }
    } else if (mode == 2) {
        // V: transposed + tf32-rounded into g_vt[b,h,d,s]
#pragma unroll
        for (int f = 0; f < 4; f++) {
#pragma unroll
            for (int j = 0; j < 4; j++) {
                int c = col0 + n0 + 8 * j + 2 * t4;
                int h = c >> 6, d = c & 63;
                float bx = bias[c], by = bias[c + 1];
#pragma unroll
                for (int rr = 0; rr < 2; rr++) {
                    int m = row0 + m0 + 16 * f + g + 8 * rr;
                    int b = m >> 11;
                    int s = m & (S_LEN - 1);
                    size_t base = ((size_t)(b * NHEAD + h) * HDIM + d) * S_LEN + s;
                    float vx = (rr == 0) ? acc[f][j].x : acc[f][j].z;
                    float vy = (rr == 0) ? acc[f][j].y : acc[f][j].w;
                    g_vt[base]         = tf32r(vx + bx);
                    g_vt[base + S_LEN] = tf32r(vy + by);
                }
            }
        }
    } else {
        float* O = (mode == 0) ? g_q : g_k;
#pragma unroll
        for (int f = 0; f < 4; f++) {
#pragma unroll
            for (int j = 0; j < 4; j++) {
                int c = col0 + n0 + 8 * j + 2 * t4;
                int h = c >> 6, d = c & 63;
                float bx = bias[c], by = bias[c + 1];
#pragma unroll
                for (int rr = 0; rr < 2; rr++) {
                    int m = row0 + m0 + 16 * f + g + 8 * rr;
                    int b = m >> 11;
                    int s = m & (S_LEN - 1);
                    size_t base = (((size_t)(b * NHEAD + h) * S_LEN + s) << 6) + d;
                    float vx = (rr == 0) ? acc[f][j].x : acc[f][j].z;
                    float vy = (rr == 0) ? acc[f][j].y : acc[f][j].w;
                    *(float2*)&O[base] = make_float2(vx + bx, vy + by);
                }
            }
        }
    }
}

// ---------------------------------------------------------------------------
// Flash attention (causal), tensor-core tf32.
// Block = (b,h, q-tile of 128). 8 warps, warp w owns q-rows 16w..16w+15.
// k-tile 64. S = QK^T via 3xTF32 (Q,K pre-split hi/lo in smem);
// PV via 2-pass (P split hi/lo, V pre-rounded tf32 from g_vt).
// Pad 68: all fragment LDS conflict-free (bank = 4g + t4 + const).
// ---------------------------------------------------------------------------
#define FP 68
#define FLASH_SMEM ((2*128*FP + 2*64*FP + 64*FP + 2*128*FP) * 4)  // 191488 B

__global__ __launch_bounds__(256, 1)
void flash_mma()
{
    extern __shared__ float sm[];
    float* Qh = sm;                  // [128][FP]
    float* Ql = Qh + 128 * FP;
    float* Kh = Ql + 128 * FP;       // [64][FP]
    float* Kl = Kh + 64 * FP;
    float* Vt = Kl + 64 * FP;        // [64][FP]  [d][s], tf32 values
    float* Ph = Vt + 64 * FP;        // [128][FP] tf32 values
    float* Pl = Ph + 128 * FP;

    const int qt  = 15 - (int)blockIdx.x;   // heavy tiles first
    const int bh  = blockIdx.y;             // b*16 + h
    const int tid = threadIdx.x;
    const int wid = tid >> 5;
    const int lane = tid & 31;
    const int g   = lane >> 2;
    const int t4  = lane & 3;
    const int m0  = wid * 16;               // warp's q-row base in tile

    const float* Qb  = g_q  + (size_t)bh * S_LEN * HDIM + (size_t)qt * 128 * HDIM;
    const float* Kb  = g_k  + (size_t)bh * S_LEN * HDIM;
    const float* Vtb = g_vt + (size_t)bh * HDIM * S_LEN;

    // stage Q tile (128x64) split hi/lo
#pragma unroll
    for (int i = 0; i < 8; i++) {
        int id = tid + 256 * i;
        int r  = id >> 4;
        int c4 = (id & 15) << 2;
        float4 q4 = *(const float4*)(Qb + (size_t)r * HDIM + c4);
        float4 hi, lo;
        split4(q4, hi, lo);
        *(float4*)&Qh[r * FP + c4] = hi;
        *(float4*)&Ql[r * FP + c4] = lo;
    }

    float4 oa[8];
#pragma unroll
    for (int j = 0; j < 8; j++) oa[j] = make_float4(0.f, 0.f, 0.f, 0.f);
    float mi0 = -1e30f, mi1 = -1e30f, li0 = 0.f, li1 = 0.f;

    const int r0g = qt * 128 + m0 + g;   // global q-row of acc .x/.y
    const int r1g = r0g + 8;             // global q-row of acc .z/.w
    const int ktmax = 2 * qt + 1;

    for (int kt = 0; kt <= ktmax; kt++) {
        __syncthreads();   // prior PV reads of K/Vt/P done
        // stage K tile (64x64) split hi/lo
#pragma unroll
        for (int i = 0; i < 4; i++) {
            int id = tid + 256 * i;
            int r  = id >> 4;
            int c4 = (id & 15) << 2;
            float4 k4 = *(const float4*)(Kb + (size_t)(kt * 64 + r) * HDIM + c4);
            float4 hi, lo;
            split4(k4, hi, lo);
            *(float4*)&Kh[r * FP + c4] = hi;
            *(float4*)&Kl[r * FP + c4] = lo;
        }
        // stage Vt tile [d][s] (already tf32-rounded)
#pragma unroll
        for (int i = 0; i < 4; i++) {
            int id = tid + 256 * i;
            int d  = id >> 4;
            int s4 = (id & 15) << 2;
            *(float4*)&Vt[d * FP + s4] =
                *(const float4*)(Vtb + (size_t)d * S_LEN + kt * 64 + s4);
        }
        __syncthreads();

        // ---- S = Q K^T (3xTF32) ----
        float4 sa[8];
#pragma unroll
        for (int j = 0; j < 8; j++) sa[j] = make_float4(0.f, 0.f, 0.f, 0.f);

#pragma unroll
        for (int kk = 0; kk < 64; kk += 8) {
            uint32_t ah[4], al[4];
            ah[0] = F2U(Qh[(m0 + g    ) * FP + kk + t4    ]);
            ah[1] = F2U(Qh[(m0 + g + 8) * FP + kk + t4    ]);
            ah[2] = F2U(Qh[(m0 + g    ) * FP + kk + t4 + 4]);
            ah[3] = F2U(Qh[(m0 + g + 8) * FP + kk + t4 + 4]);
            al[0] = F2U(Ql[(m0 + g    ) * FP + kk + t4    ]);
            al[1] = F2U(Ql[(m0 + g + 8) * FP + kk + t4    ]);
            al[2] = F2U(Ql[(m0 + g    ) * FP + kk + t4 + 4]);
            al[3] = F2U(Ql[(m0 + g + 8) * FP + kk + t4 + 4]);
#pragma unroll
            for (int j = 0; j < 8; j++) {
                uint32_t bh0 = F2U(Kh[(8 * j + g) * FP + kk + t4    ]);
                uint32_t bh1 = F2U(Kh[(8 * j + g) * FP + kk + t4 + 4]);
                uint32_t bl0 = F2U(Kl[(8 * j + g) * FP + kk + t4    ]);
                uint32_t bl1 = F2U(Kl[(8 * j + g) * FP + kk + t4 + 4]);
                mma_tf32(sa[j], ah, bh0, bh1);
                mma_tf32(sa[j], ah, bl0, bl1);
                mma_tf32(sa[j], al, bh0, bh1);
            }
        }

        // ---- scale + causal mask ----
        if (kt >= 2 * qt) {
#pragma unroll
            for (int j = 0; j < 8; j++) {
                int c0 = kt * 64 + 8 * j + 2 * t4;
                int c1 = c0 + 1;
                sa[j].x = (c0 > r0g) ? -1e30f : sa[j].x * 0.125f;
                sa[j].y = (c1 > r0g) ? -1e30f : sa[j].y * 0.125f;
                sa[j].z = (c0 > r1g) ? -1e30f : sa[j].z * 0.125f;
                sa[j].w = (c1 > r1g) ? -1e30f : sa[j].w * 0.125f;
            }
        } else {
#pragma unroll
            for (int j = 0; j < 8; j++) {
                sa[j].x *= 0.125f; sa[j].y *= 0.125f;
                sa[j].z *= 0.125f; sa[j].w *= 0.125f;
            }
        }

        // ---- online softmax (row stats: reduce over t4 lanes) ----
        float rmax0 = -1e30f, rmax1 = -1e30f;
#pragma unroll
        for (int j = 0; j < 8; j++) {
            rmax0 = fmaxf(rmax0, fmaxf(sa[j].x, sa[j].y));
            rmax1 = fmaxf(rmax1, fmaxf(sa[j].z, sa[j].w));
        }
        rmax0 = fmaxf(rmax0, __shfl_xor_sync(0xffffffffu, rmax0, 1));
        rmax0 = fmaxf(rmax0, __shfl_xor_sync(0xffffffffu, rmax0, 2));
        rmax1 = fmaxf(rmax1, __shfl_xor_sync(0xffffffffu, rmax1, 1));
        rmax1 = fmaxf(rmax1, __shfl_xor_sync(0xffffffffu, rmax1, 2));

        float mnew0 = fmaxf(mi0, rmax0);
        float mnew1 = fmaxf(mi1, rmax1);

        float rs0 = 0.f, rs1 = 0.f;
#pragma unroll
        for (int j = 0; j < 8; j++) {
            sa[j].x = __expf(sa[j].x - mnew0);
            sa[j].y = __expf(sa[j].y - mnew0);
            sa[j].z = __expf(sa[j].z - mnew1);
            sa[j].w = __expf(sa[j].w - mnew1);
            rs0 += sa[j].x + sa[j].y;
            rs1 += sa[j].z + sa[j].w;
        }
        rs0 += __shfl_xor_sync(0xffffffffu, rs0, 1);
        rs0 += __shfl_xor_sync(0xffffffffu, rs0, 2);
        rs1 += __shfl_xor_sync(0xffffffffu, rs1, 1);
        rs1 += __shfl_xor_sync(0xffffffffu, rs1, 2);

        float a0 = __expf(mi0 - mnew0);
        float a1 = __expf(mi1 - mnew1);
        li0 = li0 * a0 + rs0; mi0 = mnew0;
        li1 = li1 * a1 + rs1; mi1 = mnew1;
#pragma unroll
        for (int j = 0; j < 8; j++) {
            oa[j].x *= a0; oa[j].y *= a0;
            oa[j].z *= a1; oa[j].w *= a1;
        }

        // ---- stage P split hi/lo (tf32 values) ----
#pragma unroll
        for (int j = 0; j < 8; j++) {
            uint32_t hx, lx, hy, ly, hz, lz, hw, lw;
            tf32_split(sa[j].x, hx, lx);
            tf32_split(sa[j].y, hy, ly);
            tf32_split(sa[j].z, hz, lz);
            tf32_split(sa[j].w, hw, lw);
            int c = 8 * j + 2 * t4;
            *(float2*)&Ph[(m0 + g    ) * FP + c] =
                make_float2(__uint_as_float(hx), __uint_as_float(hy));
            *(float2*)&Ph[(m0 + g + 8) * FP + c] =
                make_float2(__uint_as_float(hz), __uint_as_float(hw));
            *(float2*)&Pl[(m0 + g    ) * FP + c] =
                make_float2(__uint_as_float(lx), __uint_as_float(ly));
            *(float2*)&Pl[(m0 + g + 8) * FP + c] =
                make_float2(__uint_as_float(lz), __uint_as_float(lw));
        }
        __syncthreads();

        // ---- O += P V (2-pass) ----
#pragma unroll
        for (int kk = 0; kk < 64; kk += 8) {
            uint32_t ph[4], pl[4];
            ph[0] = F2U(Ph[(m0 + g    ) * FP + kk + t4    ]);
            ph[1] = F2U(Ph[(m0 + g + 8) * FP + kk + t4    ]);
            ph[2] = F2U(Ph[(m0 + g    ) * FP + kk + t4 + 4]);
            ph[3] = F2U(Ph[(m0 + g + 8) * FP + kk + t4 + 4]);
            pl[0] = F2U(Pl[(m0 + g    ) * FP + kk + t4    ]);
            pl[1] = F2U(Pl[(m0 + g + 8) * FP + kk + t4    ]);
            pl[2] = F2U(Pl[(m0 + g    ) * FP + kk + t4 + 4]);
            pl[3] = F2U(Pl[(m0 + g + 8) * FP + kk + t4 + 4]);
#pragma unroll
            for (int j = 0; j < 8; j++) {
                uint32_t b0 = F2U(Vt[(8 * j + g) * FP + kk + t4    ]);
                uint32_t b1 = F2U(Vt[(8 * j + g) * FP + kk + t4 + 4]);
                mma_tf32(oa[j], ph, b0, b1);
                mma_tf32(oa[j], pl, b0, b1);
            }
        }
    }

    // ---- normalize + write [B,S,E] for output projection ----
    float inv0 = 1.f / li0;
    float inv1 = 1.f / li1;
    int b = bh >> 4, h = bh & 15;
#pragma unroll
    for (int j = 0; j < 8; j++) {
        int c = h * 64 + 8 * j + 2 * t4;
        *(float2*)&g_att[(size_t)(b * S_LEN + r0g) * EMB + c] =
            make_float2(oa[j].x * inv0, oa[j].y * inv0);
        *(float2*)&g_att[(size_t)(b * S_LEN + r1g) * EMB + c] =
            make_float2(oa[j].z * inv1, oa[j].w * inv1);
    }
}

// ---------------------------------------------------------------------------
// inputs: 0=x 1=mask 2=Wq 3=bq 4=Wk 5=bk 6=Wv 7=bv 8=Wo 9=bo
// ---------------------------------------------------------------------------
extern "C" void kernel_launch(void* const* d_in, const int* in_sizes, int n_in,
                              void* d_out, int out_size)
{
    (void)in_sizes; (void)n_in; (void)out_size;
    const float* x  = (const float*)d_in[0];
    const float* Wq = (const float*)d_in[2];
    const float* bq = (const float*)d_in[3];
    const float* Wk = (const float*)d_in[4];
    const float* bk = (const float*)d_in[5];
    const float* Wv = (const float*)d_in[6];
    const float* bv = (const float*)d_in[7];
    const float* Wo = (const float*)d_in[8];
    const float* bo = (const float*)d_in[9];
    float* out = (float*)d_out;

    // fused QKV projections: grid.z selects Q/K/V
    dim3 gqkv(EMB / 128, MROWS / 128, 3);
    sgemm_tf32<<<gqkv, 256>>>(x, Wq, Wk, Wv, bq, bk, bv, nullptr, -1);

    cudaFuncSetAttribute(flash_mma,
                         cudaFuncAttributeMaxDynamicSharedMemorySize, FLASH_SMEM);
    flash_mma<<<dim3(16, BATCH * NHEAD), 256, FLASH_SMEM>>>();

    dim3 gg(EMB / 128, MROWS / 128, 1);
    sgemm_tf32<<<gg, 256>>>(x, Wo, nullptr, nullptr, bo, nullptr, nullptr, out, 3);
}

// round 13
// speedup vs baseline: 7.2308x; 1.0961x over previous
#include <cuda_runtime.h>
#include <cuda_bf16.h>
#include <cstdint>

#define S_LEN 2048
#define EMB   1024
#define NHEAD 16
#define HDIM  64
#define BATCH 2
#define MROWS 4096   // BATCH * S_LEN

// Scratch (allocation-free rule: __device__ globals)
__device__ __align__(16) float g_q [BATCH * NHEAD * S_LEN * HDIM];  // [B,H,S,D]
__device__ __align__(16) float g_k [BATCH * NHEAD * S_LEN * HDIM];  // [B,H,S,D]
__device__ __align__(16) float g_vt[BATCH * NHEAD * HDIM * S_LEN];  // [B,H,D,S] tf32-rounded
__device__ __align__(16) float g_att[BATCH * S_LEN * EMB];          // [B,S,E]

// ---------------------------------------------------------------------------
// 3xTF32 helpers
// ---------------------------------------------------------------------------
__device__ __forceinline__ void tf32_split(float x, uint32_t& hi, uint32_t& lo)
{
    uint32_t h;
    asm("cvt.rna.tf32.f32 %0, %1;" : "=r"(h) : "f"(x));
    float r = x - __uint_as_float(h);   // exact
    uint32_t l;
    asm("cvt.rna.tf32.f32 %0, %1;" : "=r"(l) : "f"(r));
    hi = h; lo = l;
}

__device__ __forceinline__ float tf32r(float x)
{
    uint32_t r;
    asm("cvt.rna.tf32.f32 %0, %1;" : "=r"(r) : "f"(x));
    return __uint_as_float(r);
}

__device__ __forceinline__ void mma_tf32(float4& d, const uint32_t a[4],
                                         uint32_t b0, uint32_t b1)
{
    asm volatile(
        "mma.sync.aligned.m16n8k8.row.col.f32.tf32.tf32.f32 "
        "{%0,%1,%2,%3}, {%4,%5,%6,%7}, {%8,%9}, {%0,%1,%2,%3};\n"
        : "+f"(d.x), "+f"(d.y), "+f"(d.z), "+f"(d.w)
        : "r"(a[0]), "r"(a[1]), "r"(a[2]), "r"(a[3]), "r"(b0), "r"(b1));
}

__device__ __forceinline__ void split4(float4 v, float4& hi, float4& lo)
{
    uint32_t h, l;
    tf32_split(v.x, h, l); hi.x = __uint_as_float(h); lo.x = __uint_as_float(l);
    tf32_split(v.y, h, l); hi.y = __uint_as_float(h); lo.y = __uint_as_float(l);
    tf32_split(v.z, h, l); hi.z = __uint_as_float(h); lo.z = __uint_as_float(l);
    tf32_split(v.w, h, l); hi.w = __uint_as_float(h); lo.w = __uint_as_float(l);
}

#define F2U(x) __float_as_uint(x)

// ---------------------------------------------------------------------------
// GEMM: C[M,N] = A[M,K] * W[N,K]^T + bias[N]   (M=4096, N=K=1024)
// 3xTF32, DOUBLE-BUFFERED + software-pipelined:
//   prefetch LDG(kb+16) -> regs, compute(stage s), split+STS(stage s^1),
//   ONE __syncthreads per iteration.
// Dynamic smem: 2 stages x {Ah,Al,Bh,Bl}[128][20] = 81920 B.
// mode_sel < 0 : fused QKV, mode = blockIdx.z (0=Q,1=K,2=V); A = x input.
//   mode 0/1 -> headed [B,H,S,D] into g_q/g_k
//   mode 2   -> transposed+tf32-rounded [B,H,D,S] into g_vt
// mode_sel == 3: A = g_att, flat output into Cflat (+bias) using W0/b0.
// ---------------------------------------------------------------------------
#define GSTG 10240                       // floats per stage (4 * 128 * 20)
#define GEMM_SMEM (2 * GSTG * 4)         // 81920 bytes

__global__ __launch_bounds__(256, 2)
void sgemm_tf32(const float* __restrict__ Ain,
                const float* __restrict__ W0, const float* __restrict__ W1,
                const float* __restrict__ W2,
                const float* __restrict__ b0p, const float* __restrict__ b1p,
                const float* __restrict__ b2p,
                float* __restrict__ Cflat, int mode_sel)
{
    extern __shared__ float gsm[];

    const int mode = (mode_sel < 0) ? (int)blockIdx.z : mode_sel;
    const float* W    = (mode == 1) ? W1 : (mode == 2) ? W2 : W0;
    const float* bias = (mode == 1) ? b1p : (mode == 2) ? b2p : b0p;
    const float* A    = (mode == 3) ? g_att : Ain;

    const int tid  = threadIdx.x;
    const int row0 = blockIdx.y * 128;
    const int col0 = blockIdx.x * 128;
    const int lane = tid & 31;
    const int wid  = tid >> 5;
    const int g    = lane >> 2;
    const int t4   = lane & 3;
    const int m0   = (wid >> 2) * 64;
    const int n0   = (wid & 3) * 32;

    // staging role: this thread loads rows r_ld and r_ld+64, k-quad kq_ld
    const int r_ld  = tid >> 2;
    const int kq_ld = (tid & 3) << 2;

    const float* Ap0 = A + (size_t)(row0 + r_ld) * EMB + kq_ld;
    const float* Ap1 = A + (size_t)(row0 + r_ld + 64) * EMB + kq_ld;
    const float* Wp0 = W + (size_t)(col0 + r_ld) * EMB + kq_ld;
    const float* Wp1 = W + (size_t)(col0 + r_ld + 64) * EMB + kq_ld;

    float4 acc[4][4];
#pragma unroll
    for (int f = 0; f < 4; f++)
#pragma unroll
        for (int j = 0; j < 4; j++)
            acc[f][j] = make_float4(0.f, 0.f, 0.f, 0.f);

    float4 pa0, pa1, pw0, pw1;

    // prologue: load + stage kb=0 into stage 0
    pa0 = *(const float4*)(Ap0);
    pa1 = *(const float4*)(Ap1);
    pw0 = *(const float4*)(Wp0);
    pw1 = *(const float4*)(Wp1);
    {
        float* Ah = gsm;
        float* Al = gsm + 2560;
        float* Bh = gsm + 5120;
        float* Bl = gsm + 7680;
        float4 hi, lo;
        split4(pa0, hi, lo);
        *(float4*)&Ah[r_ld * 20 + kq_ld] = hi; *(float4*)&Al[r_ld * 20 + kq_ld] = lo;
        split4(pa1, hi, lo);
        *(float4*)&Ah[(r_ld + 64) * 20 + kq_ld] = hi; *(float4*)&Al[(r_ld + 64) * 20 + kq_ld] = lo;
        split4(pw0, hi, lo);
        *(float4*)&Bh[r_ld * 20 + kq_ld] = hi; *(float4*)&Bl[r_ld * 20 + kq_ld] = lo;
        split4(pw1, hi, lo);
        *(float4*)&Bh[(r_ld + 64) * 20 + kq_ld] = hi; *(float4*)&Bl[(r_ld + 64) * 20 + kq_ld] = lo;
    }
    __syncthreads();

    int st = 0;
    for (int kb = 0; kb < EMB; kb += 16) {
        const bool more = (kb + 16 < EMB);
        if (more) {   // prefetch next tile into registers (overlaps compute)
            pa0 = *(const float4*)(Ap0 + kb + 16);
            pa1 = *(const float4*)(Ap1 + kb + 16);
            pw0 = *(const float4*)(Wp0 + kb + 16);
            pw1 = *(const float4*)(Wp1 + kb + 16);
        }

        const float* Ah = gsm + st * GSTG;
        const float* Al = Ah + 2560;
        const float* Bh = Ah + 5120;
        const float* Bl = Ah + 7680;

#pragma unroll
        for (int kk = 0; kk < 16; kk += 8) {
            uint32_t ah[4][4], al[4][4];
#pragma unroll
            for (int f = 0; f < 4; f++) {
                ah[f][0] = F2U(Ah[(m0 + 16 * f + g    ) * 20 + kk + t4    ]);
                ah[f][1] = F2U(Ah[(m0 + 16 * f + g + 8) * 20 + kk + t4    ]);
                ah[f][2] = F2U(Ah[(m0 + 16 * f + g    ) * 20 + kk + t4 + 4]);
                ah[f][3] = F2U(Ah[(m0 + 16 * f + g + 8) * 20 + kk + t4 + 4]);
                al[f][0] = F2U(Al[(m0 + 16 * f + g    ) * 20 + kk + t4    ]);
                al[f][1] = F2U(Al[(m0 + 16 * f + g + 8) * 20 + kk + t4    ]);
                al[f][2] = F2U(Al[(m0 + 16 * f + g    ) * 20 + kk + t4 + 4]);
                al[f][3] = F2U(Al[(m0 + 16 * f + g + 8) * 20 + kk + t4 + 4]);
            }
#pragma unroll
            for (int j = 0; j < 4; j++) {
                uint32_t bh0 = F2U(Bh[(n0 + 8 * j + g) * 20 + kk + t4    ]);
                uint32_t bh1 = F2U(Bh[(n0 + 8 * j + g) * 20 + kk + t4 + 4]);
                uint32_t bl0 = F2U(Bl[(n0 + 8 * j + g) * 20 + kk + t4    ]);
                uint32_t bl1 = F2U(Bl[(n0 + 8 * j + g) * 20 + kk + t4 + 4]);
#pragma unroll
                for (int f = 0; f < 4; f++) {
                    mma_tf32(acc[f][j], ah[f], bh0, bh1);
                    mma_tf32(acc[f][j], ah[f], bl0, bl1);
                    mma_tf32(acc[f][j], al[f], bh0, bh1);
                }
            }
        }

        if (more) {   // split + store into the other stage
            float* Ah2 = gsm + (st ^ 1) * GSTG;
            float* Al2 = Ah2 + 2560;
            float* Bh2 = Ah2 + 5120;
            float* Bl2 = Ah2 + 7680;
            float4 hi, lo;
            split4(pa0, hi, lo);
            *(float4*)&Ah2[r_ld * 20 + kq_ld] = hi; *(float4*)&Al2[r_ld * 20 + kq_ld] = lo;
            split4(pa1, hi, lo);
            *(float4*)&Ah2[(r_ld + 64) * 20 + kq_ld] = hi; *(float4*)&Al2[(r_ld + 64) * 20 + kq_ld] = lo;
            split4(pw0, hi, lo);
            *(float4*)&Bh2[r_ld * 20 + kq_ld] = hi; *(float4*)&Bl2[r_ld * 20 + kq_ld] = lo;
            split4(pw1, hi, lo);
            *(float4*)&Bh2[(r_ld + 64) * 20 + kq_ld] = hi; *(float4*)&Bl2[(r_ld + 64) * 20 + kq_ld] = lo;
            __syncthreads();
        }
        st ^= 1;
    }

    if (mode == 3) {
#pragma unroll
        for (int f = 0; f < 4; f++) {
            int r1 = row0 + m0 + 16 * f + g;
#pragma unroll
            for (int j = 0; j < 4; j++) {
                int c  = col0 + n0 + 8 * j + 2 * t4;
                float bx = bias[c], by = bias[c + 1];
                *(float2*)&Cflat[(size_t)r1 * EMB + c] =
                    make_float2(acc[f][j].x + bx, acc[f][j].y + by);
                *(float2*)&Cflat[(size_t)(r1 + 8) * EMB + c] =
                    make_float2(acc[f][j].z + bx, acc[f][j].w + by);
            }
        }
    } else if (mode == 2) {
        // V: transposed + tf32-rounded into g_vt[b,h,d,s]
#pragma unroll
        for (int f = 0; f < 4; f++) {
#pragma unroll
            for (int j = 0; j < 4; j++) {
                int c = col0 + n0 + 8 * j + 2 * t4;
                int h = c >> 6, d = c & 63;
                float bx = bias[c], by = bias[c + 1];
#pragma unroll
                for (int rr = 0; rr < 2; rr++) {
                    int m = row0 + m0 + 16 * f + g + 8 * rr;
                    int b = m >> 11;
                    int s = m & (S_LEN - 1);
                    size_t base = ((size_t)(b * NHEAD + h) * HDIM + d) * S_LEN + s;
                    float vx = (rr == 0) ? acc[f][j].x : acc[f][j].z;
                    float vy = (rr == 0) ? acc[f][j].y : acc[f][j].w;
                    g_vt[base]         = tf32r(vx + bx);
                    g_vt[base + S_LEN] = tf32r(vy + by);
                }
            }
        }
    } else {
        float* O = (mode == 0) ? g_q : g_k;
#pragma unroll
        for (int f = 0; f < 4; f++) {
#pragma unroll
            for (int j = 0; j < 4; j++) {
                int c = col0 + n0 + 8 * j + 2 * t4;
                int h = c >> 6, d = c & 63;
                float bx = bias[c], by = bias[c + 1];
#pragma unroll
                for (int rr = 0; rr < 2; rr++) {
                    int m = row0 + m0 + 16 * f + g + 8 * rr;
                    int b = m >> 11;
                    int s = m & (S_LEN - 1);
                    size_t base = (((size_t)(b * NHEAD + h) * S_LEN + s) << 6) + d;
                    float vx = (rr == 0) ? acc[f][j].x : acc[f][j].z;
                    float vy = (rr == 0) ? acc[f][j].y : acc[f][j].w;
                    *(float2*)&O[base] = make_float2(vx + bx, vy + by);
                }
            }
        }
    }
}

// ---------------------------------------------------------------------------
// Flash attention (causal), tensor-core tf32 (unchanged from R11-best).
// ---------------------------------------------------------------------------
#define FP 68
#define FLASH_SMEM ((2*128*FP + 2*64*FP + 64*FP + 2*128*FP) * 4)  // 191488 B

__global__ __launch_bounds__(256, 1)
void flash_mma()
{
    extern __shared__ float sm[];
    float* Qh = sm;                  // [128][FP]
    float* Ql = Qh + 128 * FP;
    float* Kh = Ql + 128 * FP;       // [64][FP]
    float* Kl = Kh + 64 * FP;
    float* Vt = Kl + 64 * FP;        // [64][FP]  [d][s], tf32 values
    float* Ph = Vt + 64 * FP;        // [128][FP] tf32 values
    float* Pl = Ph + 128 * FP;

    const int qt  = 15 - (int)blockIdx.x;   // heavy tiles first
    const int bh  = blockIdx.y;             // b*16 + h
    const int tid = threadIdx.x;
    const int wid = tid >> 5;
    const int lane = tid & 31;
    const int g   = lane >> 2;
    const int t4  = lane & 3;
    const int m0  = wid * 16;               // warp's q-row base in tile

    const float* Qb  = g_q  + (size_t)bh * S_LEN * HDIM + (size_t)qt * 128 * HDIM;
    const float* Kb  = g_k  + (size_t)bh * S_LEN * HDIM;
    const float* Vtb = g_vt + (size_t)bh * HDIM * S_LEN;

    // stage Q tile (128x64) split hi/lo
#pragma unroll
    for (int i = 0; i < 8; i++) {
        int id = tid + 256 * i;
        int r  = id >> 4;
        int c4 = (id & 15) << 2;
        float4 q4 = *(const float4*)(Qb + (size_t)r * HDIM + c4);
        float4 hi, lo;
        split4(q4, hi, lo);
        *(float4*)&Qh[r * FP + c4] = hi;
        *(float4*)&Ql[r * FP + c4] = lo;
    }

    float4 oa[8];
#pragma unroll
    for (int j = 0; j < 8; j++) oa[j] = make_float4(0.f, 0.f, 0.f, 0.f);
    float mi0 = -1e30f, mi1 = -1e30f, li0 = 0.f, li1 = 0.f;

    const int r0g = qt * 128 + m0 + g;   // global q-row of acc .x/.y
    const int r1g = r0g + 8;             // global q-row of acc .z/.w
    const int ktmax = 2 * qt + 1;

    for (int kt = 0; kt <= ktmax; kt++) {
        __syncthreads();   // prior PV reads of K/Vt/P done
        // stage K tile (64x64) split hi/lo
#pragma unroll
        for (int i = 0; i < 4; i++) {
            int id = tid + 256 * i;
            int r  = id >> 4;
            int c4 = (id & 15) << 2;
            float4 k4 = *(const float4*)(Kb + (size_t)(kt * 64 + r) * HDIM + c4);
            float4 hi, lo;
            split4(k4, hi, lo);
            *(float4*)&Kh[r * FP + c4] = hi;
            *(float4*)&Kl[r * FP + c4] = lo;
        }
        // stage Vt tile [d][s] (already tf32-rounded)
#pragma unroll
        for (int i = 0; i < 4; i++) {
            int id = tid + 256 * i;
            int d  = id >> 4;
            int s4 = (id & 15) << 2;
            *(float4*)&Vt[d * FP + s4] =
                *(const float4*)(Vtb + (size_t)d * S_LEN + kt * 64 + s4);
        }
        __syncthreads();

        // ---- S = Q K^T (3xTF32) ----
        float4 sa[8];
#pragma unroll
        for (int j = 0; j < 8; j++) sa[j] = make_float4(0.f, 0.f, 0.f, 0.f);

#pragma unroll
        for (int kk = 0; kk < 64; kk += 8) {
            uint32_t ah[4], al[4];
            ah[0] = F2U(Qh[(m0 + g    ) * FP + kk + t4    ]);
            ah[1] = F2U(Qh[(m0 + g + 8) * FP + kk + t4    ]);
            ah[2] = F2U(Qh[(m0 + g    ) * FP + kk + t4 + 4]);
            ah[3] = F2U(Qh[(m0 + g + 8) * FP + kk + t4 + 4]);
            al[0] = F2U(Ql[(m0 + g    ) * FP + kk + t4    ]);
            al[1] = F2U(Ql[(m0 + g + 8) * FP + kk + t4    ]);
            al[2] = F2U(Ql[(m0 + g    ) * FP + kk + t4 + 4]);
            al[3] = F2U(Ql[(m0 + g + 8) * FP + kk + t4 + 4]);
#pragma unroll
            for (int j = 0; j < 8; j++) {
                uint32_t bh0 = F2U(Kh[(8 * j + g) * FP + kk + t4    ]);
                uint32_t bh1 = F2U(Kh[(8 * j + g) * FP + kk + t4 + 4]);
                uint32_t bl0 = F2U(Kl[(8 * j + g) * FP + kk + t4    ]);
                uint32_t bl1 = F2U(Kl[(8 * j + g) * FP + kk + t4 + 4]);
                mma_tf32(sa[j], ah, bh0, bh1);
                mma_tf32(sa[j], ah, bl0, bl1);
                mma_tf32(sa[j], al, bh0, bh1);
            }
        }

        // ---- scale + causal mask ----
        if (kt >= 2 * qt) {
#pragma unroll
            for (int j = 0; j < 8; j++) {
                int c0 = kt * 64 + 8 * j + 2 * t4;
                int c1 = c0 + 1;
                sa[j].x = (c0 > r0g) ? -1e30f : sa[j].x * 0.125f;
                sa[j].y = (c1 > r0g) ? -1e30f : sa[j].y * 0.125f;
                sa[j].z = (c0 > r1g) ? -1e30f : sa[j].z * 0.125f;
                sa[j].w = (c1 > r1g) ? -1e30f : sa[j].w * 0.125f;
            }
        } else {
#pragma unroll
            for (int j = 0; j < 8; j++) {
                sa[j].x *= 0.125f; sa[j].y *= 0.125f;
                sa[j].z *= 0.125f; sa[j].w *= 0.125f;
            }
        }

        // ---- online softmax (row stats: reduce over t4 lanes) ----
        float rmax0 = -1e30f, rmax1 = -1e30f;
#pragma unroll
        for (int j = 0; j < 8; j++) {
            rmax0 = fmaxf(rmax0, fmaxf(sa[j].x, sa[j].y));
            rmax1 = fmaxf(rmax1, fmaxf(sa[j].z, sa[j].w));
        }
        rmax0 = fmaxf(rmax0, __shfl_xor_sync(0xffffffffu, rmax0, 1));
        rmax0 = fmaxf(rmax0, __shfl_xor_sync(0xffffffffu, rmax0, 2));
        rmax1 = fmaxf(rmax1, __shfl_xor_sync(0xffffffffu, rmax1, 1));
        rmax1 = fmaxf(rmax1, __shfl_xor_sync(0xffffffffu, rmax1, 2));

        float mnew0 = fmaxf(mi0, rmax0);
        float mnew1 = fmaxf(mi1, rmax1);

        float rs0 = 0.f, rs1 = 0.f;
#pragma unroll
        for (int j = 0; j < 8; j++) {
            sa[j].x = __expf(sa[j].x - mnew0);
            sa[j].y = __expf(sa[j].y - mnew0);
            sa[j].z = __expf(sa[j].z - mnew1);
            sa[j].w = __expf(sa[j].w - mnew1);
            rs0 += sa[j].x + sa[j].y;
            rs1 += sa[j].z + sa[j].w;
        }
        rs0 += __shfl_xor_sync(0xffffffffu, rs0, 1);
        rs0 += __shfl_xor_sync(0xffffffffu, rs0, 2);
        rs1 += __shfl_xor_sync(0xffffffffu, rs1, 1);
        rs1 += __shfl_xor_sync(0xffffffffu, rs1, 2);

        float a0 = __expf(mi0 - mnew0);
        float a1 = __expf(mi1 - mnew1);
        li0 = li0 * a0 + rs0; mi0 = mnew0;
        li1 = li1 * a1 + rs1; mi1 = mnew1;
#pragma unroll
        for (int j = 0; j < 8; j++) {
            oa[j].x *= a0; oa[j].y *= a0;
            oa[j].z *= a1; oa[j].w *= a1;
        }

        // ---- stage P split hi/lo (tf32 values) ----
#pragma unroll
        for (int j = 0; j < 8; j++) {
            uint32_t hx, lx, hy, ly, hz, lz, hw, lw;
            tf32_split(sa[j].x, hx, lx);
            tf32_split(sa[j].y, hy, ly);
            tf32_split(sa[j].z, hz, lz);
            tf32_split(sa[j].w, hw, lw);
            int c = 8 * j + 2 * t4;
            *(float2*)&Ph[(m0 + g    ) * FP + c] =
                make_float2(__uint_as_float(hx), __uint_as_float(hy));
            *(float2*)&Ph[(m0 + g + 8) * FP + c] =
                make_float2(__uint_as_float(hz), __uint_as_float(hw));
            *(float2*)&Pl[(m0 + g    ) * FP + c] =
                make_float2(__uint_as_float(lx), __uint_as_float(ly));
            *(float2*)&Pl[(m0 + g + 8) * FP + c] =
                make_float2(__uint_as_float(lz), __uint_as_float(lw));
        }
        __syncthreads();

        // ---- O += P V (2-pass) ----
#pragma unroll
        for (int kk = 0; kk < 64; kk += 8) {
            uint32_t ph[4], pl[4];
            ph[0] = F2U(Ph[(m0 + g    ) * FP + kk + t4    ]);
            ph[1] = F2U(Ph[(m0 + g + 8) * FP + kk + t4    ]);
            ph[2] = F2U(Ph[(m0 + g    ) * FP + kk + t4 + 4]);
            ph[3] = F2U(Ph[(m0 + g + 8) * FP + kk + t4 + 4]);
            pl[0] = F2U(Pl[(m0 + g    ) * FP + kk + t4    ]);
            pl[1] = F2U(Pl[(m0 + g + 8) * FP + kk + t4    ]);
            pl[2] = F2U(Pl[(m0 + g    ) * FP + kk + t4 + 4]);
            pl[3] = F2U(Pl[(m0 + g + 8) * FP + kk + t4 + 4]);
#pragma unroll
            for (int j = 0; j < 8; j++) {
                uint32_t b0 = F2U(Vt[(8 * j + g) * FP + kk + t4    ]);
                uint32_t b1 = F2U(Vt[(8 * j + g) * FP + kk + t4 + 4]);
                mma_tf32(oa[j], ph, b0, b1);
                mma_tf32(oa[j], pl, b0, b1);
            }
        }
    }

    // ---- normalize + write [B,S,E] for output projection ----
    float inv0 = 1.f / li0;
    float inv1 = 1.f / li1;
    int b = bh >> 4, h = bh & 15;
#pragma unroll
    for (int j = 0; j < 8; j++) {
        int c = h * 64 + 8 * j + 2 * t4;
        *(float2*)&g_att[(size_t)(b * S_LEN + r0g) * EMB + c] =
            make_float2(oa[j].x * inv0, oa[j].y * inv0);
        *(float2*)&g_att[(size_t)(b * S_LEN + r1g) * EMB + c] =
            make_float2(oa[j].z * inv1, oa[j].w * inv1);
    }
}

// ---------------------------------------------------------------------------
// inputs: 0=x 1=mask 2=Wq 3=bq 4=Wk 5=bk 6=Wv 7=bv 8=Wo 9=bo
// ---------------------------------------------------------------------------
extern "C" void kernel_launch(void* const* d_in, const int* in_sizes, int n_in,
                              void* d_out, int out_size)
{
    (void)in_sizes; (void)n_in; (void)out_size;
    const float* x  = (const float*)d_in[0];
    const float* Wq = (const float*)d_in[2];
    const float* bq = (const float*)d_in[3];
    const float* Wk = (const float*)d_in[4];
    const float* bk = (const float*)d_in[5];
    const float* Wv = (const float*)d_in[6];
    const float* bv = (const float*)d_in[7];
    const float* Wo = (const float*)d_in[8];
    const float* bo = (const float*)d_in[9];
    float* out = (float*)d_out;

    cudaFuncSetAttribute(sgemm_tf32,
                         cudaFuncAttributeMaxDynamicSharedMemorySize, GEMM_SMEM);
    cudaFuncSetAttribute(flash_mma,
                         cudaFuncAttributeMaxDynamicSharedMemorySize, FLASH_SMEM);

    // fused QKV projections: grid.z selects Q/K/V
    dim3 gqkv(EMB / 128, MROWS / 128, 3);
    sgemm_tf32<<<gqkv, 256, GEMM_SMEM>>>(x, Wq, Wk, Wv, bq, bk, bv, nullptr, -1);

    flash_mma<<<dim3(16, BATCH * NHEAD), 256, FLASH_SMEM>>>();

    dim3 gg(EMB / 128, MROWS / 128, 1);
    sgemm_tf32<<<gg, 256, GEMM_SMEM>>>(x, Wo, nullptr, nullptr, bo, nullptr, nullptr, out, 3);
}

// round 14
// speedup vs baseline: 7.2750x; 1.0061x over previous
#include <cuda_runtime.h>
#include <cuda_bf16.h>
#include <cstdint>

#define S_LEN 2048
#define EMB   1024
#define NHEAD 16
#define HDIM  64
#define BATCH 2
#define MROWS 4096   // BATCH * S_LEN

// Scratch (allocation-free rule: __device__ globals)
__device__ __align__(16) float g_q [BATCH * NHEAD * S_LEN * HDIM];  // [B,H,S,D]
__device__ __align__(16) float g_k [BATCH * NHEAD * S_LEN * HDIM];  // [B,H,S,D]
__device__ __align__(16) float g_vt[BATCH * NHEAD * HDIM * S_LEN];  // [B,H,D,S] tf32-rounded
__device__ __align__(16) float g_att[BATCH * S_LEN * EMB];          // [B,S,E]

// ---------------------------------------------------------------------------
// 3xTF32 helpers
// ---------------------------------------------------------------------------
__device__ __forceinline__ void tf32_split(float x, uint32_t& hi, uint32_t& lo)
{
    uint32_t h;
    asm("cvt.rna.tf32.f32 %0, %1;" : "=r"(h) : "f"(x));
    float r = x - __uint_as_float(h);   // exact
    uint32_t l;
    asm("cvt.rna.tf32.f32 %0, %1;" : "=r"(l) : "f"(r));
    hi = h; lo = l;
}

__device__ __forceinline__ float tf32r(float x)
{
    uint32_t r;
    asm("cvt.rna.tf32.f32 %0, %1;" : "=r"(r) : "f"(x));
    return __uint_as_float(r);
}

__device__ __forceinline__ void mma_tf32(float4& d, const uint32_t a[4],
                                         uint32_t b0, uint32_t b1)
{
    asm volatile(
        "mma.sync.aligned.m16n8k8.row.col.f32.tf32.tf32.f32 "
        "{%0,%1,%2,%3}, {%4,%5,%6,%7}, {%8,%9}, {%0,%1,%2,%3};\n"
        : "+f"(d.x), "+f"(d.y), "+f"(d.z), "+f"(d.w)
        : "r"(a[0]), "r"(a[1]), "r"(a[2]), "r"(a[3]), "r"(b0), "r"(b1));
}

__device__ __forceinline__ void split4(float4 v, float4& hi, float4& lo)
{
    uint32_t h, l;
    tf32_split(v.x, h, l); hi.x = __uint_as_float(h); lo.x = __uint_as_float(l);
    tf32_split(v.y, h, l); hi.y = __uint_as_float(h); lo.y = __uint_as_float(l);
    tf32_split(v.z, h, l); hi.z = __uint_as_float(h); lo.z = __uint_as_float(l);
    tf32_split(v.w, h, l); hi.w = __uint_as_float(h); lo.w = __uint_as_float(l);
}

#define F2U(x) __float_as_uint(x)

// ---------------------------------------------------------------------------
// GEMM: C[M,N] = A[M,K] * W[N,K]^T + bias[N]   (M=4096, N=K=1024)
// 3xTF32, double-buffered + software-pipelined + PASS-MAJOR mma scheduling:
// the 3 split passes are separate sweeps over all (j,f) so dependent mmas to
// the same accumulator are 16 mmas apart (>= mma latency).
// ---------------------------------------------------------------------------
#define GSTG 10240                       // floats per stage (4 * 128 * 20)
#define GEMM_SMEM (2 * GSTG * 4)         // 81920 bytes

__global__ __launch_bounds__(256, 2)
void sgemm_tf32(const float* __restrict__ Ain,
                const float* __restrict__ W0, const float* __restrict__ W1,
                const float* __restrict__ W2,
                const float* __restrict__ b0p, const float* __restrict__ b1p,
                const float* __restrict__ b2p,
                float* __restrict__ Cflat, int mode_sel)
{
    extern __shared__ float gsm[];

    const int mode = (mode_sel < 0) ? (int)blockIdx.z : mode_sel;
    const float* W    = (mode == 1) ? W1 : (mode == 2) ? W2 : W0;
    const float* bias = (mode == 1) ? b1p : (mode == 2) ? b2p : b0p;
    const float* A    = (mode == 3) ? g_att : Ain;

    const int tid  = threadIdx.x;
    const int row0 = blockIdx.y * 128;
    const int col0 = blockIdx.x * 128;
    const int lane = tid & 31;
    const int wid  = tid >> 5;
    const int g    = lane >> 2;
    const int t4   = lane & 3;
    const int m0   = (wid >> 2) * 64;
    const int n0   = (wid & 3) * 32;

    const int r_ld  = tid >> 2;
    const int kq_ld = (tid & 3) << 2;

    const float* Ap0 = A + (size_t)(row0 + r_ld) * EMB + kq_ld;
    const float* Ap1 = A + (size_t)(row0 + r_ld + 64) * EMB + kq_ld;
    const float* Wp0 = W + (size_t)(col0 + r_ld) * EMB + kq_ld;
    const float* Wp1 = W + (size_t)(col0 + r_ld + 64) * EMB + kq_ld;

    float4 acc[4][4];
#pragma unroll
    for (int f = 0; f < 4; f++)
#pragma unroll
        for (int j = 0; j < 4; j++)
            acc[f][j] = make_float4(0.f, 0.f, 0.f, 0.f);

    float4 pa0, pa1, pw0, pw1;

    // prologue: load + stage kb=0 into stage 0
    pa0 = *(const float4*)(Ap0);
    pa1 = *(const float4*)(Ap1);
    pw0 = *(const float4*)(Wp0);
    pw1 = *(const float4*)(Wp1);
    {
        float* Ah = gsm;
        float* Al = gsm + 2560;
        float* Bh = gsm + 5120;
        float* Bl = gsm + 7680;
        float4 hi, lo;
        split4(pa0, hi, lo);
        *(float4*)&Ah[r_ld * 20 + kq_ld] = hi; *(float4*)&Al[r_ld * 20 + kq_ld] = lo;
        split4(pa1, hi, lo);
        *(float4*)&Ah[(r_ld + 64) * 20 + kq_ld] = hi; *(float4*)&Al[(r_ld + 64) * 20 + kq_ld] = lo;
        split4(pw0, hi, lo);
        *(float4*)&Bh[r_ld * 20 + kq_ld] = hi; *(float4*)&Bl[r_ld * 20 + kq_ld] = lo;
        split4(pw1, hi, lo);
        *(float4*)&Bh[(r_ld + 64) * 20 + kq_ld] = hi; *(float4*)&Bl[(r_ld + 64) * 20 + kq_ld] = lo;
    }
    __syncthreads();

    int st = 0;
    for (int kb = 0; kb < EMB; kb += 16) {
        const bool more = (kb + 16 < EMB);
        if (more) {   // prefetch next tile into registers (overlaps compute)
            pa0 = *(const float4*)(Ap0 + kb + 16);
            pa1 = *(const float4*)(Ap1 + kb + 16);
            pw0 = *(const float4*)(Wp0 + kb + 16);
            pw1 = *(const float4*)(Wp1 + kb + 16);
        }

        const float* Ah = gsm + st * GSTG;
        const float* Al = Ah + 2560;
        const float* Bh = Ah + 5120;
        const float* Bl = Ah + 7680;

#pragma unroll
        for (int kk = 0; kk < 16; kk += 8) {
            uint32_t ah[4][4], al[4][4];
#pragma unroll
            for (int f = 0; f < 4; f++) {
                ah[f][0] = F2U(Ah[(m0 + 16 * f + g    ) * 20 + kk + t4    ]);
                ah[f][1] = F2U(Ah[(m0 + 16 * f + g + 8) * 20 + kk + t4    ]);
                ah[f][2] = F2U(Ah[(m0 + 16 * f + g    ) * 20 + kk + t4 + 4]);
                ah[f][3] = F2U(Ah[(m0 + 16 * f + g + 8) * 20 + kk + t4 + 4]);
                al[f][0] = F2U(Al[(m0 + 16 * f + g    ) * 20 + kk + t4    ]);
                al[f][1] = F2U(Al[(m0 + 16 * f + g + 8) * 20 + kk + t4    ]);
                al[f][2] = F2U(Al[(m0 + 16 * f + g    ) * 20 + kk + t4 + 4]);
                al[f][3] = F2U(Al[(m0 + 16 * f + g + 8) * 20 + kk + t4 + 4]);
            }
            uint32_t bh[4][2], bl[4][2];
#pragma unroll
            for (int j = 0; j < 4; j++) {
                bh[j][0] = F2U(Bh[(n0 + 8 * j + g) * 20 + kk + t4    ]);
                bh[j][1] = F2U(Bh[(n0 + 8 * j + g) * 20 + kk + t4 + 4]);
                bl[j][0] = F2U(Bl[(n0 + 8 * j + g) * 20 + kk + t4    ]);
                bl[j][1] = F2U(Bl[(n0 + 8 * j + g) * 20 + kk + t4 + 4]);
            }
            // pass-major: same-acc touches are 16 mmas apart
#pragma unroll
            for (int j = 0; j < 4; j++)
#pragma unroll
                for (int f = 0; f < 4; f++)
                    mma_tf32(acc[f][j], ah[f], bh[j][0], bh[j][1]);
#pragma unroll
            for (int j = 0; j < 4; j++)
#pragma unroll
                for (int f = 0; f < 4; f++)
                    mma_tf32(acc[f][j], ah[f], bl[j][0], bl[j][1]);
#pragma unroll
            for (int j = 0; j < 4; j++)
#pragma unroll
                for (int f = 0; f < 4; f++)
                    mma_tf32(acc[f][j], al[f], bh[j][0], bh[j][1]);
        }

        if (more) {   // split + store into the other stage
            float* Ah2 = gsm + (st ^ 1) * GSTG;
            float* Al2 = Ah2 + 2560;
            float* Bh2 = Ah2 + 5120;
            float* Bl2 = Ah2 + 7680;
            float4 hi, lo;
            split4(pa0, hi, lo);
            *(float4*)&Ah2[r_ld * 20 + kq_ld] = hi; *(float4*)&Al2[r_ld * 20 + kq_ld] = lo;
            split4(pa1, hi, lo);
            *(float4*)&Ah2[(r_ld + 64) * 20 + kq_ld] = hi; *(float4*)&Al2[(r_ld + 64) * 20 + kq_ld] = lo;
            split4(pw0, hi, lo);
            *(float4*)&Bh2[r_ld * 20 + kq_ld] = hi; *(float4*)&Bl2[r_ld * 20 + kq_ld] = lo;
            split4(pw1, hi, lo);
            *(float4*)&Bh2[(r_ld + 64) * 20 + kq_ld] = hi; *(float4*)&Bl2[(r_ld + 64) * 20 + kq_ld] = lo;
            __syncthreads();
        }
        st ^= 1;
    }

    if (mode == 3) {
#pragma unroll
        for (int f = 0; f < 4; f++) {
            int r1 = row0 + m0 + 16 * f + g;
#pragma unroll
            for (int j = 0; j < 4; j++) {
                int c  = col0 + n0 + 8 * j + 2 * t4;
                float bx = bias[c], by = bias[c + 1];
                *(float2*)&Cflat[(size_t)r1 * EMB + c] =
                    make_float2(acc[f][j].x + bx, acc[f][j].y + by);
                *(float2*)&Cflat[(size_t)(r1 + 8) * EMB + c] =
                    make_float2(acc[f][j].z + bx, acc[f][j].w + by);
            }
        }
    } else if (mode == 2) {
        // V: transposed + tf32-rounded into g_vt[b,h,d,s]
#pragma unroll
        for (int f = 0; f < 4; f++) {
#pragma unroll
            for (int j = 0; j < 4; j++) {
                int c = col0 + n0 + 8 * j + 2 * t4;
                int h = c >> 6, d = c & 63;
                float bx = bias[c], by = bias[c + 1];
#pragma unroll
                for (int rr = 0; rr < 2; rr++) {
                    int m = row0 + m0 + 16 * f + g + 8 * rr;
                    int b = m >> 11;
                    int s = m & (S_LEN - 1);
                    size_t base = ((size_t)(b * NHEAD + h) * HDIM + d) * S_LEN + s;
                    float vx = (rr == 0) ? acc[f][j].x : acc[f][j].z;
                    float vy = (rr == 0) ? acc[f][j].y : acc[f][j].w;
                    g_vt[base]         = tf32r(vx + bx);
                    g_vt[base + S_LEN] = tf32r(vy + by);
                }
            }
        }
    } else {
        float* O = (mode == 0) ? g_q : g_k;
#pragma unroll
        for (int f = 0; f < 4; f++) {
#pragma unroll
            for (int j = 0; j < 4; j++) {
                int c = col0 + n0 + 8 * j + 2 * t4;
                int h = c >> 6, d = c & 63;
                float bx = bias[c], by = bias[c + 1];
#pragma unroll
                for (int rr = 0; rr < 2; rr++) {
                    int m = row0 + m0 + 16 * f + g + 8 * rr;
                    int b = m >> 11;
                    int s = m & (S_LEN - 1);
                    size_t base = (((size_t)(b * NHEAD + h) * S_LEN + s) << 6) + d;
                    float vx = (rr == 0) ? acc[f][j].x : acc[f][j].z;
                    float vy = (rr == 0) ? acc[f][j].y : acc[f][j].w;
                    *(float2*)&O[base] = make_float2(vx + bx, vy + by);
                }
            }
        }
    }
}

// ---------------------------------------------------------------------------
// Flash attention (causal), tensor-core tf32, pass-major mma scheduling
// (4-wide j-chunks: same-acc touches separated by 4 independent mmas).
// ---------------------------------------------------------------------------
#define FP 68
#define FLASH_SMEM ((2*128*FP + 2*64*FP + 64*FP + 2*128*FP) * 4)  // 191488 B

__global__ __launch_bounds__(256, 1)
void flash_mma()
{
    extern __shared__ float sm[];
    float* Qh = sm;                  // [128][FP]
    float* Ql = Qh + 128 * FP;
    float* Kh = Ql + 128 * FP;       // [64][FP]
    float* Kl = Kh + 64 * FP;
    float* Vt = Kl + 64 * FP;        // [64][FP]  [d][s], tf32 values
    float* Ph = Vt + 64 * FP;        // [128][FP] tf32 values
    float* Pl = Ph + 128 * FP;

    const int qt  = 15 - (int)blockIdx.x;   // heavy tiles first
    const int bh  = blockIdx.y;             // b*16 + h
    const int tid = threadIdx.x;
    const int wid = tid >> 5;
    const int lane = tid & 31;
    const int g   = lane >> 2;
    const int t4  = lane & 3;
    const int m0  = wid * 16;               // warp's q-row base in tile

    const float* Qb  = g_q  + (size_t)bh * S_LEN * HDIM + (size_t)qt * 128 * HDIM;
    const float* Kb  = g_k  + (size_t)bh * S_LEN * HDIM;
    const float* Vtb = g_vt + (size_t)bh * HDIM * S_LEN;

    // stage Q tile (128x64) split hi/lo
#pragma unroll
    for (int i = 0; i < 8; i++) {
        int id = tid + 256 * i;
        int r  = id >> 4;
        int c4 = (id & 15) << 2;
        float4 q4 = *(const float4*)(Qb + (size_t)r * HDIM + c4);
        float4 hi, lo;
        split4(q4, hi, lo);
        *(float4*)&Qh[r * FP + c4] = hi;
        *(float4*)&Ql[r * FP + c4] = lo;
    }

    float4 oa[8];
#pragma unroll
    for (int j = 0; j < 8; j++) oa[j] = make_float4(0.f, 0.f, 0.f, 0.f);
    float mi0 = -1e30f, mi1 = -1e30f, li0 = 0.f, li1 = 0.f;

    const int r0g = qt * 128 + m0 + g;   // global q-row of acc .x/.y
    const int r1g = r0g + 8;             // global q-row of acc .z/.w
    const int ktmax = 2 * qt + 1;

    for (int kt = 0; kt <= ktmax; kt++) {
        __syncthreads();   // prior PV reads of K/Vt/P done
        // stage K tile (64x64) split hi/lo
#pragma unroll
        for (int i = 0; i < 4; i++) {
            int id = tid + 256 * i;
            int r  = id >> 4;
            int c4 = (id & 15) << 2;
            float4 k4 = *(const float4*)(Kb + (size_t)(kt * 64 + r) * HDIM + c4);
            float4 hi, lo;
            split4(k4, hi, lo);
            *(float4*)&Kh[r * FP + c4] = hi;
            *(float4*)&Kl[r * FP + c4] = lo;
        }
        // stage Vt tile [d][s] (already tf32-rounded)
#pragma unroll
        for (int i = 0; i < 4; i++) {
            int id = tid + 256 * i;
            int d  = id >> 4;
            int s4 = (id & 15) << 2;
            *(float4*)&Vt[d * FP + s4] =
                *(const float4*)(Vtb + (size_t)d * S_LEN + kt * 64 + s4);
        }
        __syncthreads();

        // ---- S = Q K^T (3xTF32, pass-major in 4-j chunks) ----
        float4 sa[8];
#pragma unroll
        for (int j = 0; j < 8; j++) sa[j] = make_float4(0.f, 0.f, 0.f, 0.f);

#pragma unroll
        for (int kk = 0; kk < 64; kk += 8) {
            uint32_t ah[4], al[4];
            ah[0] = F2U(Qh[(m0 + g    ) * FP + kk + t4    ]);
            ah[1] = F2U(Qh[(m0 + g + 8) * FP + kk + t4    ]);
            ah[2] = F2U(Qh[(m0 + g    ) * FP + kk + t4 + 4]);
            ah[3] = F2U(Qh[(m0 + g + 8) * FP + kk + t4 + 4]);
            al[0] = F2U(Ql[(m0 + g    ) * FP + kk + t4    ]);
            al[1] = F2U(Ql[(m0 + g + 8) * FP + kk + t4    ]);
            al[2] = F2U(Ql[(m0 + g    ) * FP + kk + t4 + 4]);
            al[3] = F2U(Ql[(m0 + g + 8) * FP + kk + t4 + 4]);
#pragma unroll
            for (int jc = 0; jc < 8; jc += 4) {
                uint32_t bh[4][2], bl[4][2];
#pragma unroll
                for (int j = 0; j < 4; j++) {
                    bh[j][0] = F2U(Kh[(8 * (jc + j) + g) * FP + kk + t4    ]);
                    bh[j][1] = F2U(Kh[(8 * (jc + j) + g) * FP + kk + t4 + 4]);
                    bl[j][0] = F2U(Kl[(8 * (jc + j) + g) * FP + kk + t4    ]);
                    bl[j][1] = F2U(Kl[(8 * (jc + j) + g) * FP + kk + t4 + 4]);
                }
#pragma unroll
                for (int j = 0; j < 4; j++)
                    mma_tf32(sa[jc + j], ah, bh[j][0], bh[j][1]);
#pragma unroll
                for (int j = 0; j < 4; j++)
                    mma_tf32(sa[jc + j], ah, bl[j][0], bl[j][1]);
#pragma unroll
                for (int j = 0; j < 4; j++)
                    mma_tf32(sa[jc + j], al, bh[j][0], bh[j][1]);
            }
        }

        // ---- scale + causal mask ----
        if (kt >= 2 * qt) {
#pragma unroll
            for (int j = 0; j < 8; j++) {
                int c0 = kt * 64 + 8 * j + 2 * t4;
                int c1 = c0 + 1;
                sa[j].x = (c0 > r0g) ? -1e30f : sa[j].x * 0.125f;
                sa[j].y = (c1 > r0g) ? -1e30f : sa[j].y * 0.125f;
                sa[j].z = (c0 > r1g) ? -1e30f : sa[j].z * 0.125f;
                sa[j].w = (c1 > r1g) ? -1e30f : sa[j].w * 0.125f;
            }
        } else {
#pragma unroll
            for (int j = 0; j < 8; j++) {
                sa[j].x *= 0.125f; sa[j].y *= 0.125f;
                sa[j].z *= 0.125f; sa[j].w *= 0.125f;
            }
        }

        // ---- online softmax (row stats: reduce over t4 lanes) ----
        float rmax0 = -1e30f, rmax1 = -1e30f;
#pragma unroll
        for (int j = 0; j < 8; j++) {
            rmax0 = fmaxf(rmax0, fmaxf(sa[j].x, sa[j].y));
            rmax1 = fmaxf(rmax1, fmaxf(sa[j].z, sa[j].w));
        }
        rmax0 = fmaxf(rmax0, __shfl_xor_sync(0xffffffffu, rmax0, 1));
        rmax0 = fmaxf(rmax0, __shfl_xor_sync(0xffffffffu, rmax0, 2));
        rmax1 = fmaxf(rmax1, __shfl_xor_sync(0xffffffffu, rmax1, 1));
        rmax1 = fmaxf(rmax1, __shfl_xor_sync(0xffffffffu, rmax1, 2));

        float mnew0 = fmaxf(mi0, rmax0);
        float mnew1 = fmaxf(mi1, rmax1);

        float rs0 = 0.f, rs1 = 0.f;
#pragma unroll
        for (int j = 0; j < 8; j++) {
            sa[j].x = __expf(sa[j].x - mnew0);
            sa[j].y = __expf(sa[j].y - mnew0);
            sa[j].z = __expf(sa[j].z - mnew1);
            sa[j].w = __expf(sa[j].w - mnew1);
            rs0 += sa[j].x + sa[j].y;
            rs1 += sa[j].z + sa[j].w;
        }
        rs0 += __shfl_xor_sync(0xffffffffu, rs0, 1);
        rs0 += __shfl_xor_sync(0xffffffffu, rs0, 2);
        rs1 += __shfl_xor_sync(0xffffffffu, rs1, 1);
        rs1 += __shfl_xor_sync(0xffffffffu, rs1, 2);

        float a0 = __expf(mi0 - mnew0);
        float a1 = __expf(mi1 - mnew1);
        li0 = li0 * a0 + rs0; mi0 = mnew0;
        li1 = li1 * a1 + rs1; mi1 = mnew1;
#pragma unroll
        for (int j = 0; j < 8; j++) {
            oa[j].x *= a0; oa[j].y *= a0;
            oa[j].z *= a1; oa[j].w *= a1;
        }

        // ---- stage P split hi/lo (tf32 values) ----
#pragma unroll
        for (int j = 0; j < 8; j++) {
            uint32_t hx, lx, hy, ly, hz, lz, hw, lw;
            tf32_split(sa[j].x, hx, lx);
            tf32_split(sa[j].y, hy, ly);
            tf32_split(sa[j].z, hz, lz);
            tf32_split(sa[j].w, hw, lw);
            int c = 8 * j + 2 * t4;
            *(float2*)&Ph[(m0 + g    ) * FP + c] =
                make_float2(__uint_as_float(hx), __uint_as_float(hy));
            *(float2*)&Ph[(m0 + g + 8) * FP + c] =
                make_float2(__uint_as_float(hz), __uint_as_float(hw));
            *(float2*)&Pl[(m0 + g    ) * FP + c] =
                make_float2(__uint_as_float(lx), __uint_as_float(ly));
            *(float2*)&Pl[(m0 + g + 8) * FP + c] =
                make_float2(__uint_as_float(lz), __uint_as_float(lw));
        }
        __syncthreads();

        // ---- O += P V (2-pass, pass-major in 4-j chunks) ----
#pragma unroll
        for (int kk = 0; kk < 64; kk += 8) {
            uint32_t ph[4], pl[4];
            ph[0] = F2U(Ph[(m0 + g    ) * FP + kk + t4    ]);
            ph[1] = F2U(Ph[(m0 + g + 8) * FP + kk + t4    ]);
            ph[2] = F2U(Ph[(m0 + g    ) * FP + kk + t4 + 4]);
            ph[3] = F2U(Ph[(m0 + g + 8) * FP + kk + t4 + 4]);
            pl[0] = F2U(Pl[(m0 + g    ) * FP + kk + t4    ]);
            pl[1] = F2U(Pl[(m0 + g + 8) * FP + kk + t4    ]);
            pl[2] = F2U(Pl[(m0 + g    ) * FP + kk + t4 + 4]);
            pl[3] = F2U(Pl[(m0 + g + 8) * FP + kk + t4 + 4]);
#pragma unroll
            for (int jc = 0; jc < 8; jc += 4) {
                uint32_t vb[4][2];
#pragma unroll
                for (int j = 0; j < 4; j++) {
                    vb[j][0] = F2U(Vt[(8 * (jc + j) + g) * FP + kk + t4    ]);
                    vb[j][1] = F2U(Vt[(8 * (jc + j) + g) * FP + kk + t4 + 4]);
                }
#pragma unroll
                for (int j = 0; j < 4; j++)
                    mma_tf32(oa[jc + j], ph, vb[j][0], vb[j][1]);
#pragma unroll
                for (int j = 0; j < 4; j++)
                    mma_tf32(oa[jc + j], pl, vb[j][0], vb[j][1]);
            }
        }
    }

    // ---- normalize + write [B,S,E] for output projection ----
    float inv0 = 1.f / li0;
    float inv1 = 1.f / li1;
    int b = bh >> 4, h = bh & 15;
#pragma unroll
    for (int j = 0; j < 8; j++) {
        int c = h * 64 + 8 * j + 2 * t4;
        *(float2*)&g_att[(size_t)(b * S_LEN + r0g) * EMB + c] =
            make_float2(oa[j].x * inv0, oa[j].y * inv0);
        *(float2*)&g_att[(size_t)(b * S_LEN + r1g) * EMB + c] =
            make_float2(oa[j].z * inv1, oa[j].w * inv1);
    }
}

// ---------------------------------------------------------------------------
// inputs: 0=x 1=mask 2=Wq 3=bq 4=Wk 5=bk 6=Wv 7=bv 8=Wo 9=bo
// ---------------------------------------------------------------------------
extern "C" void kernel_launch(void* const* d_in, const int* in_sizes, int n_in,
                              void* d_out, int out_size)
{
    (void)in_sizes; (void)n_in; (void)out_size;
    const float* x  = (const float*)d_in[0];
    const float* Wq = (const float*)d_in[2];
    const float* bq = (const float*)d_in[3];
    const float* Wk = (const float*)d_in[4];
    const float* bk = (const float*)d_in[5];
    const float* Wv = (const float*)d_in[6];
    const float* bv = (const float*)d_in[7];
    const float* Wo = (const float*)d_in[8];
    const float* bo = (const float*)d_in[9];
    float* out = (float*)d_out;

    cudaFuncSetAttribute(sgemm_tf32,
                         cudaFuncAttributeMaxDynamicSharedMemorySize, GEMM_SMEM);
    cudaFuncSetAttribute(flash_mma,
                         cudaFuncAttributeMaxDynamicSharedMemorySize, FLASH_SMEM);

    // fused QKV projections: grid.z selects Q/K/V
    dim3 gqkv(EMB / 128, MROWS / 128, 3);
    sgemm_tf32<<<gqkv, 256, GEMM_SMEM>>>(x, Wq, Wk, Wv, bq, bk, bv, nullptr, -1);

    flash_mma<<<dim3(16, BATCH * NHEAD), 256, FLASH_SMEM>>>();

    dim3 gg(EMB / 128, MROWS / 128, 1);
    sgemm_tf32<<<gg, 256, GEMM_SMEM>>>(x, Wo, nullptr, nullptr, bo, nullptr, nullptr, out, 3);
}

// round 15
// speedup vs baseline: 9.9342x; 1.3655x over previous
#include <cuda_runtime.h>
#include <cuda_bf16.h>
#include <cstdint>

#define S_LEN 2048
#define EMB   1024
#define NHEAD 16
#define HDIM  64
#define BATCH 2
#define MROWS 4096   // BATCH * S_LEN

// Scratch (allocation-free rule: __device__ globals)
__device__ __align__(16) float g_q [BATCH * NHEAD * S_LEN * HDIM];  // [B,H,S,D]
__device__ __align__(16) float g_k [BATCH * NHEAD * S_LEN * HDIM];  // [B,H,S,D]
__device__ __align__(16) float g_vt[BATCH * NHEAD * HDIM * S_LEN];  // [B,H,D,S] tf32-rounded
__device__ __align__(16) float g_att[BATCH * S_LEN * EMB];          // [B,S,E]

// ---------------------------------------------------------------------------
// helpers
// ---------------------------------------------------------------------------
__device__ __forceinline__ void tf32_split(float x, uint32_t& hi, uint32_t& lo)
{
    uint32_t h;
    asm("cvt.rna.tf32.f32 %0, %1;" : "=r"(h) : "f"(x));
    float r = x - __uint_as_float(h);   // exact
    uint32_t l;
    asm("cvt.rna.tf32.f32 %0, %1;" : "=r"(l) : "f"(r));
    hi = h; lo = l;
}

__device__ __forceinline__ float tf32r(float x)
{
    uint32_t r;
    asm("cvt.rna.tf32.f32 %0, %1;" : "=r"(r) : "f"(x));
    return __uint_as_float(r);
}

__device__ __forceinline__ void mma_tf32(float4& d, const uint32_t a[4],
                                         uint32_t b0, uint32_t b1)
{
    asm volatile(
        "mma.sync.aligned.m16n8k8.row.col.f32.tf32.tf32.f32 "
        "{%0,%1,%2,%3}, {%4,%5,%6,%7}, {%8,%9}, {%0,%1,%2,%3};\n"
        : "+f"(d.x), "+f"(d.y), "+f"(d.z), "+f"(d.w)
        : "r"(a[0]), "r"(a[1]), "r"(a[2]), "r"(a[3]), "r"(b0), "r"(b1));
}

__device__ __forceinline__ void mma_bf16(float4& d, const uint32_t a[4],
                                         uint32_t b0, uint32_t b1)
{
    asm volatile(
        "mma.sync.aligned.m16n8k16.row.col.f32.bf16.bf16.f32 "
        "{%0,%1,%2,%3}, {%4,%5,%6,%7}, {%8,%9}, {%0,%1,%2,%3};\n"
        : "+f"(d.x), "+f"(d.y), "+f"(d.z), "+f"(d.w)
        : "r"(a[0]), "r"(a[1]), "r"(a[2]), "r"(a[3]), "r"(b0), "r"(b1));
}

__device__ __forceinline__ void ldsm_x4(uint32_t r[4], uint32_t addr)
{
    asm volatile("ldmatrix.sync.aligned.m8n8.x4.shared.b16 {%0,%1,%2,%3}, [%4];"
        : "=r"(r[0]), "=r"(r[1]), "=r"(r[2]), "=r"(r[3]) : "r"(addr));
}

__device__ __forceinline__ void ldsm_x2(uint32_t r[2], uint32_t addr)
{
    asm volatile("ldmatrix.sync.aligned.m8n8.x2.shared.b16 {%0,%1}, [%2];"
        : "=r"(r[0]), "=r"(r[1]) : "r"(addr));
}

__device__ __forceinline__ void split4(float4 v, float4& hi, float4& lo)
{
    uint32_t h, l;
    tf32_split(v.x, h, l); hi.x = __uint_as_float(h); lo.x = __uint_as_float(l);
    tf32_split(v.y, h, l); hi.y = __uint_as_float(h); lo.y = __uint_as_float(l);
    tf32_split(v.z, h, l); hi.z = __uint_as_float(h); lo.z = __uint_as_float(l);
    tf32_split(v.w, h, l); hi.w = __uint_as_float(h); lo.w = __uint_as_float(l);
}

// bf16 split: x = hi + lo (each bf16). Packs two columns into one b32 word.
__device__ __forceinline__ void bsplit2(float x, float y, uint32_t& hi, uint32_t& lo)
{
    __nv_bfloat162 h = __floats2bfloat162_rn(x, y);
    float rx = x - __bfloat162float(h.x);
    float ry = y - __bfloat162float(h.y);
    __nv_bfloat162 l = __floats2bfloat162_rn(rx, ry);
    hi = *reinterpret_cast<uint32_t*>(&h);
    lo = *reinterpret_cast<uint32_t*>(&l);
}

#define F2U(x) __float_as_uint(x)

// ---------------------------------------------------------------------------
// GEMM: C[M,N] = A[M,K] * W[N,K]^T + bias[N]   (M=4096, N=K=1024)
// bf16x3 + ldmatrix. 128x128 tile, BK=16 stages, double-buffered.
// smem per stage: Ah/Al/Bh/Bl [128][24] bf16 (pitch 24 = conflict-free LDSM).
// 3 passes: ah*bh, ah*bl, al*bh (al*bl dropped, ~2^-16 rel).
// ---------------------------------------------------------------------------
#define GP     24                        // bf16 pitch
#define G_AH   0                         // byte offsets within stage
#define G_AL   6144
#define G_BH   12288
#define G_BL   18432
#define G_STAGE 24576                    // bytes per stage
#define GEMM_SMEM (2 * G_STAGE)          // 49152

__global__ __launch_bounds__(256, 2)
void sgemm_bf16(const float* __restrict__ Ain,
                const float* __restrict__ W0, const float* __restrict__ W1,
                const float* __restrict__ W2,
                const float* __restrict__ b0p, const float* __restrict__ b1p,
                const float* __restrict__ b2p,
                float* __restrict__ Cflat, int mode_sel)
{
    extern __shared__ __align__(16) char gsm[];

    const int mode = (mode_sel < 0) ? (int)blockIdx.z : mode_sel;
    const float* W    = (mode == 1) ? W1 : (mode == 2) ? W2 : W0;
    const float* bias = (mode == 1) ? b1p : (mode == 2) ? b2p : b0p;
    const float* A    = (mode == 3) ? g_att : Ain;

    const int tid  = threadIdx.x;
    const int row0 = blockIdx.y * 128;
    const int col0 = blockIdx.x * 128;
    const int lane = tid & 31;
    const int wid  = tid >> 5;
    const int g    = lane >> 2;
    const int t4   = lane & 3;
    const int m0   = (wid >> 2) * 64;
    const int n0   = (wid & 3) * 32;

    // staging role: row r_ld, 8 k-columns at kq
    const int r_ld = tid >> 1;
    const int kq   = (tid & 1) * 8;

    const float* Ap = A + (size_t)(row0 + r_ld) * EMB + kq;
    const float* Wp = W + (size_t)(col0 + r_ld) * EMB + kq;

    const uint32_t sb = (uint32_t)__cvta_generic_to_shared(gsm);
    const uint32_t st_addr = sb + (uint32_t)(r_ld * GP + kq) * 2;   // + plane off

    // ldmatrix lane-address components
    const int a_row = (lane & 7) + ((lane >> 3) & 1) * 8;   // 0..15
    const int a_col = (lane >> 4) * 8;                      // 0 or 8
    const int b_row = lane & 7;
    const int b_col = ((lane >> 3) & 1) * 8;

    uint32_t aA[4], aB[4];   // frag base addrs (stage 0), A-hi / B-hi
#pragma unroll
    for (int f = 0; f < 4; f++)
        aA[f] = sb + (uint32_t)((m0 + 16 * f + a_row) * GP + a_col) * 2;
#pragma unroll
    for (int j = 0; j < 4; j++)
        aB[j] = sb + G_BH + (uint32_t)((n0 + 8 * j + b_row) * GP + b_col) * 2;

    float4 acc[4][4];
#pragma unroll
    for (int f = 0; f < 4; f++)
#pragma unroll
        for (int j = 0; j < 4; j++)
            acc[f][j] = make_float4(0.f, 0.f, 0.f, 0.f);

    float4 pa0, pa1, pw0, pw1;

    // prologue: stage kb=0 into stage 0
    pa0 = *(const float4*)(Ap);
    pa1 = *(const float4*)(Ap + 4);
    pw0 = *(const float4*)(Wp);
    pw1 = *(const float4*)(Wp + 4);
    {
        uint4 hi, lo;
        bsplit2(pa0.x, pa0.y, hi.x, lo.x);
        bsplit2(pa0.z, pa0.w, hi.y, lo.y);
        bsplit2(pa1.x, pa1.y, hi.z, lo.z);
        bsplit2(pa1.z, pa1.w, hi.w, lo.w);
        asm volatile("st.shared.v4.b32 [%0], {%1,%2,%3,%4};" ::
            "r"(st_addr + G_AH), "r"(hi.x), "r"(hi.y), "r"(hi.z), "r"(hi.w));
        asm volatile("st.shared.v4.b32 [%0], {%1,%2,%3,%4};" ::
            "r"(st_addr + G_AL), "r"(lo.x), "r"(lo.y), "r"(lo.z), "r"(lo.w));
        bsplit2(pw0.x, pw0.y, hi.x, lo.x);
        bsplit2(pw0.z, pw0.w, hi.y, lo.y);
        bsplit2(pw1.x, pw1.y, hi.z, lo.z);
        bsplit2(pw1.z, pw1.w, hi.w, lo.w);
        asm volatile("st.shared.v4.b32 [%0], {%1,%2,%3,%4};" ::
            "r"(st_addr + G_BH), "r"(hi.x), "r"(hi.y), "r"(hi.z), "r"(hi.w));
        asm volatile("st.shared.v4.b32 [%0], {%1,%2,%3,%4};" ::
            "r"(st_addr + G_BL), "r"(lo.x), "r"(lo.y), "r"(lo.z), "r"(lo.w));
    }
    __syncthreads();

    uint32_t soff = 0;   // stage byte offset
    for (int kb = 0; kb < EMB; kb += 16) {
        const bool more = (kb + 16 < EMB);
        if (more) {   // prefetch next k-block (overlaps compute)
            pa0 = *(const float4*)(Ap + kb + 16);
            pa1 = *(const float4*)(Ap + kb + 20);
            pw0 = *(const float4*)(Wp + kb + 16);
            pw1 = *(const float4*)(Wp + kb + 20);
        }

        uint32_t ah[4][4], bh[4][2], bl[4][2];
#pragma unroll
        for (int f = 0; f < 4; f++) ldsm_x4(ah[f], aA[f] + soff);          // A hi
#pragma unroll
        for (int j = 0; j < 4; j++) ldsm_x2(bh[j], aB[j] + soff);          // B hi
#pragma unroll
        for (int j = 0; j < 4; j++)
#pragma unroll
            for (int f = 0; f < 4; f++)
                mma_bf16(acc[f][j], ah[f], bh[j][0], bh[j][1]);            // hh
#pragma unroll
        for (int j = 0; j < 4; j++) ldsm_x2(bl[j], aB[j] + soff + (G_BL - G_BH));
#pragma unroll
        for (int j = 0; j < 4; j++)
#pragma unroll
            for (int f = 0; f < 4; f++)
                mma_bf16(acc[f][j], ah[f], bl[j][0], bl[j][1]);            // hl
#pragma unroll
        for (int f = 0; f < 4; f++) ldsm_x4(ah[f], aA[f] + soff + G_AL);   // A lo
#pragma unroll
        for (int j = 0; j < 4; j++)
#pragma unroll
            for (int f = 0; f < 4; f++)
                mma_bf16(acc[f][j], ah[f], bh[j][0], bh[j][1]);            // lh

        if (more) {
            uint32_t st2 = st_addr + (soff ^ G_STAGE);
            uint4 hi, lo;
            bsplit2(pa0.x, pa0.y, hi.x, lo.x);
            bsplit2(pa0.z, pa0.w, hi.y, lo.y);
            bsplit2(pa1.x, pa1.y, hi.z, lo.z);
            bsplit2(pa1.z, pa1.w, hi.w, lo.w);
            asm volatile("st.shared.v4.b32 [%0], {%1,%2,%3,%4};" ::
                "r"(st2 + G_AH), "r"(hi.x), "r"(hi.y), "r"(hi.z), "r"(hi.w));
            asm volatile("st.shared.v4.b32 [%0], {%1,%2,%3,%4};" ::
                "r"(st2 + G_AL), "r"(lo.x), "r"(lo.y), "r"(lo.z), "r"(lo.w));
            bsplit2(pw0.x, pw0.y, hi.x, lo.x);
            bsplit2(pw0.z, pw0.w, hi.y, lo.y);
            bsplit2(pw1.x, pw1.y, hi.z, lo.z);
            bsplit2(pw1.z, pw1.w, hi.w, lo.w);
            asm volatile("st.shared.v4.b32 [%0], {%1,%2,%3,%4};" ::
                "r"(st2 + G_BH), "r"(hi.x), "r"(hi.y), "r"(hi.z), "r"(hi.w));
            asm volatile("st.shared.v4.b32 [%0], {%1,%2,%3,%4};" ::
                "r"(st2 + G_BL), "r"(lo.x), "r"(lo.y), "r"(lo.z), "r"(lo.w));
            __syncthreads();
        }
        soff ^= G_STAGE;
    }

    if (mode == 3) {
#pragma unroll
        for (int f = 0; f < 4; f++) {
            int r1 = row0 + m0 + 16 * f + g;
#pragma unroll
            for (int j = 0; j < 4; j++) {
                int c  = col0 + n0 + 8 * j + 2 * t4;
                float bx = bias[c], by = bias[c + 1];
                *(float2*)&Cflat[(size_t)r1 * EMB + c] =
                    make_float2(acc[f][j].x + bx, acc[f][j].y + by);
                *(float2*)&Cflat[(size_t)(r1 + 8) * EMB + c] =
                    make_float2(acc[f][j].z + bx, acc[f][j].w + by);
            }
        }
    } else if (mode == 2) {
        // V: transposed + tf32-rounded into g_vt[b,h,d,s]
#pragma unroll
        for (int f = 0; f < 4; f++) {
#pragma unroll
            for (int j = 0; j < 4; j++) {
                int c = col0 + n0 + 8 * j + 2 * t4;
                int h = c >> 6, d = c & 63;
                float bx = bias[c], by = bias[c + 1];
#pragma unroll
                for (int rr = 0; rr < 2; rr++) {
                    int m = row0 + m0 + 16 * f + g + 8 * rr;
                    int b = m >> 11;
                    int s = m & (S_LEN - 1);
                    size_t base = ((size_t)(b * NHEAD + h) * HDIM + d) * S_LEN + s;
                    float vx = (rr == 0) ? acc[f][j].x : acc[f][j].z;
                    float vy = (rr == 0) ? acc[f][j].y : acc[f][j].w;
                    g_vt[base]         = tf32r(vx + bx);
                    g_vt[base + S_LEN] = tf32r(vy + by);
                }
            }
        }
    } else {
        float* O = (mode == 0) ? g_q : g_k;
#pragma unroll
        for (int f = 0; f < 4; f++) {
#pragma unroll
            for (int j = 0; j < 4; j++) {
                int c = col0 + n0 + 8 * j + 2 * t4;
                int h = c >> 6, d = c & 63;
                float bx = bias[c], by = bias[c + 1];
#pragma unroll
                for (int rr = 0; rr < 2; rr++) {
                    int m = row0 + m0 + 16 * f + g + 8 * rr;
                    int b = m >> 11;
                    int s = m & (S_LEN - 1);
                    size_t base = (((size_t)(b * NHEAD + h) * S_LEN + s) << 6) + d;
                    float vx = (rr == 0) ? acc[f][j].x : acc[f][j].z;
                    float vy = (rr == 0) ? acc[f][j].y : acc[f][j].w;
                    *(float2*)&O[base] = make_float2(vx + bx, vy + by);
                }
            }
        }
    }
}

// ---------------------------------------------------------------------------
// Flash attention (causal), tensor-core tf32 (unchanged from R14-best).
// ---------------------------------------------------------------------------
#define FP 68
#define FLASH_SMEM ((2*128*FP + 2*64*FP + 64*FP + 2*128*FP) * 4)  // 191488 B

__global__ __launch_bounds__(256, 1)
void flash_mma()
{
    extern __shared__ float sm[];
    float* Qh = sm;                  // [128][FP]
    float* Ql = Qh + 128 * FP;
    float* Kh = Ql + 128 * FP;       // [64][FP]
    float* Kl = Kh + 64 * FP;
    float* Vt = Kl + 64 * FP;        // [64][FP]  [d][s], tf32 values
    float* Ph = Vt + 64 * FP;        // [128][FP] tf32 values
    float* Pl = Ph + 128 * FP;

    const int qt  = 15 - (int)blockIdx.x;   // heavy tiles first
    const int bh  = blockIdx.y;             // b*16 + h
    const int tid = threadIdx.x;
    const int wid = tid >> 5;
    const int lane = tid & 31;
    const int g   = lane >> 2;
    const int t4  = lane & 3;
    const int m0  = wid * 16;               // warp's q-row base in tile

    const float* Qb  = g_q  + (size_t)bh * S_LEN * HDIM + (size_t)qt * 128 * HDIM;
    const float* Kb  = g_k  + (size_t)bh * S_LEN * HDIM;
    const float* Vtb = g_vt + (size_t)bh * HDIM * S_LEN;

    // stage Q tile (128x64) split hi/lo
#pragma unroll
    for (int i = 0; i < 8; i++) {
        int id = tid + 256 * i;
        int r  = id >> 4;
        int c4 = (id & 15) << 2;
        float4 q4 = *(const float4*)(Qb + (size_t)r * HDIM + c4);
        float4 hi, lo;
        split4(q4, hi, lo);
        *(float4*)&Qh[r * FP + c4] = hi;
        *(float4*)&Ql[r * FP + c4] = lo;
    }

    float4 oa[8];
#pragma unroll
    for (int j = 0; j < 8; j++) oa[j] = make_float4(0.f, 0.f, 0.f, 0.f);
    float mi0 = -1e30f, mi1 = -1e30f, li0 = 0.f, li1 = 0.f;

    const int r0g = qt * 128 + m0 + g;   // global q-row of acc .x/.y
    const int r1g = r0g + 8;             // global q-row of acc .z/.w
    const int ktmax = 2 * qt + 1;

    for (int kt = 0; kt <= ktmax; kt++) {
        __syncthreads();   // prior PV reads of K/Vt/P done
        // stage K tile (64x64) split hi/lo
#pragma unroll
        for (int i = 0; i < 4; i++) {
            int id = tid + 256 * i;
            int r  = id >> 4;
            int c4 = (id & 15) << 2;
            float4 k4 = *(const float4*)(Kb + (size_t)(kt * 64 + r) * HDIM + c4);
            float4 hi, lo;
            split4(k4, hi, lo);
            *(float4*)&Kh[r * FP + c4] = hi;
            *(float4*)&Kl[r * FP + c4] = lo;
        }
        // stage Vt tile [d][s] (already tf32-rounded)
#pragma unroll
        for (int i = 0; i < 4; i++) {
            int id = tid + 256 * i;
            int d  = id >> 4;
            int s4 = (id & 15) << 2;
            *(float4*)&Vt[d * FP + s4] =
                *(const float4*)(Vtb + (size_t)d * S_LEN + kt * 64 + s4);
        }
        __syncthreads();

        // ---- S = Q K^T (3xTF32, pass-major in 4-j chunks) ----
        float4 sa[8];
#pragma unroll
        for (int j = 0; j < 8; j++) sa[j] = make_float4(0.f, 0.f, 0.f, 0.f);

#pragma unroll
        for (int kk = 0; kk < 64; kk += 8) {
            uint32_t ah[4], al[4];
            ah[0] = F2U(Qh[(m0 + g    ) * FP + kk + t4    ]);
            ah[1] = F2U(Qh[(m0 + g + 8) * FP + kk + t4    ]);
            ah[2] = F2U(Qh[(m0 + g    ) * FP + kk + t4 + 4]);
            ah[3] = F2U(Qh[(m0 + g + 8) * FP + kk + t4 + 4]);
            al[0] = F2U(Ql[(m0 + g    ) * FP + kk + t4    ]);
            al[1] = F2U(Ql[(m0 + g + 8) * FP + kk + t4    ]);
            al[2] = F2U(Ql[(m0 + g    ) * FP + kk + t4 + 4]);
            al[3] = F2U(Ql[(m0 + g + 8) * FP + kk + t4 + 4]);
#pragma unroll
            for (int jc = 0; jc < 8; jc += 4) {
                uint32_t bh[4][2], bl[4][2];
#pragma unroll
                for (int j = 0; j < 4; j++) {
                    bh[j][0] = F2U(Kh[(8 * (jc + j) + g) * FP + kk + t4    ]);
                    bh[j][1] = F2U(Kh[(8 * (jc + j) + g) * FP + kk + t4 + 4]);
                    bl[j][0] = F2U(Kl[(8 * (jc + j) + g) * FP + kk + t4    ]);
                    bl[j][1] = F2U(Kl[(8 * (jc + j) + g) * FP + kk + t4 + 4]);
                }
#pragma unroll
                for (int j = 0; j < 4; j++)
                    mma_tf32(sa[jc + j], ah, bh[j][0], bh[j][1]);
#pragma unroll
                for (int j = 0; j < 4; j++)
                    mma_tf32(sa[jc + j], ah, bl[j][0], bl[j][1]);
#pragma unroll
                for (int j = 0; j < 4; j++)
                    mma_tf32(sa[jc + j], al, bh[j][0], bh[j][1]);
            }
        }

        // ---- scale + causal mask ----
        if (kt >= 2 * qt) {
#pragma unroll
            for (int j = 0; j < 8; j++) {
                int c0 = kt * 64 + 8 * j + 2 * t4;
                int c1 = c0 + 1;
                sa[j].x = (c0 > r0g) ? -1e30f : sa[j].x * 0.125f;
                sa[j].y = (c1 > r0g) ? -1e30f : sa[j].y * 0.125f;
                sa[j].z = (c0 > r1g) ? -1e30f : sa[j].z * 0.125f;
                sa[j].w = (c1 > r1g) ? -1e30f : sa[j].w * 0.125f;
            }
        } else {
#pragma unroll
            for (int j = 0; j < 8; j++) {
                sa[j].x *= 0.125f; sa[j].y *= 0.125f;
                sa[j].z *= 0.125f; sa[j].w *= 0.125f;
            }
        }

        // ---- online softmax (row stats: reduce over t4 lanes) ----
        float rmax0 = -1e30f, rmax1 = -1e30f;
#pragma unroll
        for (int j = 0; j < 8; j++) {
            rmax0 = fmaxf(rmax0, fmaxf(sa[j].x, sa[j].y));
            rmax1 = fmaxf(rmax1, fmaxf(sa[j].z, sa[j].w));
        }
        rmax0 = fmaxf(rmax0, __shfl_xor_sync(0xffffffffu, rmax0, 1));
        rmax0 = fmaxf(rmax0, __shfl_xor_sync(0xffffffffu, rmax0, 2));
        rmax1 = fmaxf(rmax1, __shfl_xor_sync(0xffffffffu, rmax1, 1));
        rmax1 = fmaxf(rmax1, __shfl_xor_sync(0xffffffffu, rmax1, 2));

        float mnew0 = fmaxf(mi0, rmax0);
        float mnew1 = fmaxf(mi1, rmax1);

        float rs0 = 0.f, rs1 = 0.f;
#pragma unroll
        for (int j = 0; j < 8; j++) {
            sa[j].x = __expf(sa[j].x - mnew0);
            sa[j].y = __expf(sa[j].y - mnew0);
            sa[j].z = __expf(sa[j].z - mnew1);
            sa[j].w = __expf(sa[j].w - mnew1);
            rs0 += sa[j].x + sa[j].y;
            rs1 += sa[j].z + sa[j].w;
        }
        rs0 += __shfl_xor_sync(0xffffffffu, rs0, 1);
        rs0 += __shfl_xor_sync(0xffffffffu, rs0, 2);
        rs1 += __shfl_xor_sync(0xffffffffu, rs1, 1);
        rs1 += __shfl_xor_sync(0xffffffffu, rs1, 2);

        float a0 = __expf(mi0 - mnew0);
        float a1 = __expf(mi1 - mnew1);
        li0 = li0 * a0 + rs0; mi0 = mnew0;
        li1 = li1 * a1 + rs1; mi1 = mnew1;
#pragma unroll
        for (int j = 0; j < 8; j++) {
            oa[j].x *= a0; oa[j].y *= a0;
            oa[j].z *= a1; oa[j].w *= a1;
        }

        // ---- stage P split hi/lo (tf32 values) ----
#pragma unroll
        for (int j = 0; j < 8; j++) {
            uint32_t hx, lx, hy, ly, hz, lz, hw, lw;
            tf32_split(sa[j].x, hx, lx);
            tf32_split(sa[j].y, hy, ly);
            tf32_split(sa[j].z, hz, lz);
            tf32_split(sa[j].w, hw, lw);
            int c = 8 * j + 2 * t4;
            *(float2*)&Ph[(m0 + g    ) * FP + c] =
                make_float2(__uint_as_float(hx), __uint_as_float(hy));
            *(float2*)&Ph[(m0 + g + 8) * FP + c] =
                make_float2(__uint_as_float(hz), __uint_as_float(hw));
            *(float2*)&Pl[(m0 + g    ) * FP + c] =
                make_float2(__uint_as_float(lx), __uint_as_float(ly));
            *(float2*)&Pl[(m0 + g + 8) * FP + c] =
                make_float2(__uint_as_float(lz), __uint_as_float(lw));
        }
        __syncthreads();

        // ---- O += P V (2-pass, pass-major in 4-j chunks) ----
#pragma unroll
        for (int kk = 0; kk < 64; kk += 8) {
            uint32_t ph[4], pl[4];
            ph[0] = F2U(Ph[(m0 + g    ) * FP + kk + t4    ]);
            ph[1] = F2U(Ph[(m0 + g + 8) * FP + kk + t4    ]);
            ph[2] = F2U(Ph[(m0 + g    ) * FP + kk + t4 + 4]);
            ph[3] = F2U(Ph[(m0 + g + 8) * FP + kk + t4 + 4]);
            pl[0] = F2U(Pl[(m0 + g    ) * FP + kk + t4    ]);
            pl[1] = F2U(Pl[(m0 + g + 8) * FP + kk + t4    ]);
            pl[2] = F2U(Pl[(m0 + g    ) * FP + kk + t4 + 4]);
            pl[3] = F2U(Pl[(m0 + g + 8) * FP + kk + t4 + 4]);
#pragma unroll
            for (int jc = 0; jc < 8; jc += 4) {
                uint32_t vb[4][2];
#pragma unroll
                for (int j = 0; j < 4; j++) {
                    vb[j][0] = F2U(Vt[(8 * (jc + j) + g) * FP + kk + t4    ]);
                    vb[j][1] = F2U(Vt[(8 * (jc + j) + g) * FP + kk + t4 + 4]);
                }
#pragma unroll
                for (int j = 0; j < 4; j++)
                    mma_tf32(oa[jc + j], ph, vb[j][0], vb[j][1]);
#pragma unroll
                for (int j = 0; j < 4; j++)
                    mma_tf32(oa[jc + j], pl, vb[j][0], vb[j][1]);
            }
        }
    }

    // ---- normalize + write [B,S,E] for output projection ----
    float inv0 = 1.f / li0;
    float inv1 = 1.f / li1;
    int b = bh >> 4, h = bh & 15;
#pragma unroll
    for (int j = 0; j < 8; j++) {
        int c = h * 64 + 8 * j + 2 * t4;
        *(float2*)&g_att[(size_t)(b * S_LEN + r0g) * EMB + c] =
            make_float2(oa[j].x * inv0, oa[j].y * inv0);
        *(float2*)&g_att[(size_t)(b * S_LEN + r1g) * EMB + c] =
            make_float2(oa[j].z * inv1, oa[j].w * inv1);
    }
}

// ---------------------------------------------------------------------------
// inputs: 0=x 1=mask 2=Wq 3=bq 4=Wk 5=bk 6=Wv 7=bv 8=Wo 9=bo
// ---------------------------------------------------------------------------
extern "C" void kernel_launch(void* const* d_in, const int* in_sizes, int n_in,
                              void* d_out, int out_size)
{
    (void)in_sizes; (void)n_in; (void)out_size;
    const float* x  = (const float*)d_in[0];
    const float* Wq = (const float*)d_in[2];
    const float* bq = (const float*)d_in[3];
    const float* Wk = (const float*)d_in[4];
    const float* bk = (const float*)d_in[5];
    const float* Wv = (const float*)d_in[6];
    const float* bv = (const float*)d_in[7];
    const float* Wo = (const float*)d_in[8];
    const float* bo = (const float*)d_in[9];
    float* out = (float*)d_out;

    cudaFuncSetAttribute(sgemm_bf16,
                         cudaFuncAttributeMaxDynamicSharedMemorySize, GEMM_SMEM);
    cudaFuncSetAttribute(flash_mma,
                         cudaFuncAttributeMaxDynamicSharedMemorySize, FLASH_SMEM);

    // fused QKV projections: grid.z selects Q/K/V
    dim3 gqkv(EMB / 128, MROWS / 128, 3);
    sgemm_bf16<<<gqkv, 256, GEMM_SMEM>>>(x, Wq, Wk, Wv, bq, bk, bv, nullptr, -1);

    flash_mma<<<dim3(16, BATCH * NHEAD), 256, FLASH_SMEM>>>();

    dim3 gg(EMB / 128, MROWS / 128, 1);
    sgemm_bf16<<<gg, 256, GEMM_SMEM>>>(x, Wo, nullptr, nullptr, bo, nullptr, nullptr, out, 3);
}